// round 12
// baseline (speedup 1.0000x reference)
#include <cuda_runtime.h>
#include <cuda_bf16.h>
#include <cstdint>
#include <math.h>

#define SEQ  2048
#define DM   1024
#define TDM  3072
#define NH   16
#define DH   64
#define MAXD 128

typedef unsigned long long ull;
typedef unsigned short u16;

// ---------------- persistent scratch (bf16 hi/lo split form) ----------------
__device__ u16 g_xh[SEQ * DM],  g_xl[SEQ * DM];
__device__ u16 g_wqh[DM * TDM], g_wql[DM * TDM];
__device__ u16 g_woh[DM * DM],  g_wol[DM * DM];
__device__ u16 g_qkvh[SEQ * TDM], g_qkvl[SEQ * TDM];
__device__ u16 g_ath[SEQ * DM],   g_atl[SEQ * DM];

// ---------------- helpers ---------------------------------------------------
__device__ __forceinline__ uint32_t smem_u32(const void* p) {
    uint32_t a;
    asm("{ .reg .u64 t; cvta.to.shared.u64 t, %1; cvt.u32.u64 %0, t; }" : "=r"(a) : "l"(p));
    return a;
}
__device__ __forceinline__ void cpa16(uint32_t dst, const void* src) {
    asm volatile("cp.async.cg.shared.global [%0], [%1], 16;" :: "r"(dst), "l"(src));
}
#define CPA_COMMIT() asm volatile("cp.async.commit_group;" ::: "memory")
#define CPA_WAIT0()  asm volatile("cp.async.wait_group 0;" ::: "memory")

__device__ __forceinline__ void ldsm_x4(uint32_t& r0, uint32_t& r1, uint32_t& r2,
                                        uint32_t& r3, uint32_t addr) {
    asm volatile("ldmatrix.sync.aligned.m8n8.x4.shared.b16 {%0,%1,%2,%3}, [%4];"
                 : "=r"(r0), "=r"(r1), "=r"(r2), "=r"(r3) : "r"(addr));
}
__device__ __forceinline__ void ldsm_x4t(uint32_t& r0, uint32_t& r1, uint32_t& r2,
                                         uint32_t& r3, uint32_t addr) {
    asm volatile("ldmatrix.sync.aligned.m8n8.x4.trans.shared.b16 {%0,%1,%2,%3}, [%4];"
                 : "=r"(r0), "=r"(r1), "=r"(r2), "=r"(r3) : "r"(addr));
}
__device__ __forceinline__ void mma16816(float* d, const uint32_t* a, const uint32_t* b) {
    asm volatile("mma.sync.aligned.m16n8k16.row.col.f32.bf16.bf16.f32 "
                 "{%0,%1,%2,%3}, {%4,%5,%6,%7}, {%8,%9}, {%0,%1,%2,%3};"
                 : "+f"(d[0]), "+f"(d[1]), "+f"(d[2]), "+f"(d[3])
                 : "r"(a[0]), "r"(a[1]), "r"(a[2]), "r"(a[3]), "r"(b[0]), "r"(b[1]));
}
__device__ __forceinline__ uint32_t bf16x2_of(float lo, float hi) {
    uint32_t r;
    asm("cvt.rn.bf16x2.f32 %0, %1, %2;" : "=r"(r) : "f"(hi), "f"(lo));
    return r;
}
__device__ __forceinline__ void pack_hilo(float x, float y, uint32_t& ph, uint32_t& pl) {
    __nv_bfloat16 hx = __float2bfloat16_rn(x);
    __nv_bfloat16 hy = __float2bfloat16_rn(y);
    float fx = __bfloat162float(hx), fy = __bfloat162float(hy);
    ph = ((uint32_t)__bfloat16_as_ushort(hy) << 16) | (uint32_t)__bfloat16_as_ushort(hx);
    pl = bf16x2_of(x - fx, y - fy);
}

// ---------------------------------------------------------------------------
// One-time fp32 -> (hi,lo) bf16 split.
// ---------------------------------------------------------------------------
__global__ __launch_bounds__(256)
void conv_split(const float* __restrict__ src, u16* __restrict__ hi,
                u16* __restrict__ lo, int n) {
    int i = (blockIdx.x * 256 + threadIdx.x) * 4;
    if (i < n) {
        float4 v = *(const float4*)(src + i);
        uint32_t h0, l0, h1, l1;
        pack_hilo(v.x, v.y, h0, l0);
        pack_hilo(v.z, v.w, h1, l1);
        *(uint32_t*)(hi + i)     = h0;
        *(uint32_t*)(hi + i + 2) = h1;
        *(uint32_t*)(lo + i)     = l0;
        *(uint32_t*)(lo + i + 2) = l1;
    }
}

// ---------------------------------------------------------------------------
// Pure-bf16 split GEMM: C = A @ B, pre-split inputs.
// CTA 64x128, 128 threads = 4 warps (2 wm x 2 wn), warp tile 32x64.
// All 12 ldmatrix per k-slice issued back-to-back, then 48 MMAs (ILP).
// ---------------------------------------------------------------------------
#define SA 40
#define SB 136
#define A_T_B 5120
#define B_T_B 8704
#define STAGE_B (2 * A_T_B + 2 * B_T_B)   // 27648
#define GSMEM   (2 * STAGE_B)             // 55296

template <bool WRITE_BF16>
__global__ __launch_bounds__(128, 4)
void gemm_bf16_v2(const u16* __restrict__ Ah, const u16* __restrict__ Al,
                  const u16* __restrict__ Bh, const u16* __restrict__ Bl,
                  float* __restrict__ Cf, u16* __restrict__ Ch, u16* __restrict__ Cl,
                  int M, int N, int K) {
    extern __shared__ char smem[];
    const uint32_t smem_b = smem_u32(smem);
    const int tid  = threadIdx.x;
    const int lane = tid & 31;
    const int wid  = tid >> 5;
    const int wm   = wid & 1;
    const int wn   = wid >> 1;
    const int bm = blockIdx.y * 64;
    const int bn = blockIdx.x * 128;

    auto load_stage = [&](int t) {
        const uint32_t stg = smem_b + (t & 1) * STAGE_B;
#pragma unroll
        for (int i = 0; i < 2; i++) {
            const int c = tid + i * 128;
            const int row = c >> 2, cc = c & 3;
            const ull sa = (ull)(bm + row) * K + t * 32 + cc * 8;
            cpa16(stg + row * 80 + cc * 16,         Ah + sa);
            cpa16(stg + A_T_B + row * 80 + cc * 16, Al + sa);
        }
#pragma unroll
        for (int i = 0; i < 4; i++) {
            const int c = tid + i * 128;
            const int rb = c >> 4, cb = c & 15;
            const ull sbp = (ull)(t * 32 + rb) * N + bn + cb * 8;
            cpa16(stg + 2 * A_T_B + rb * 272 + cb * 16,         Bh + sbp);
            cpa16(stg + 2 * A_T_B + B_T_B + rb * 272 + cb * 16, Bl + sbp);
        }
    };

    float accM0[8][4], accM1[8][4];
#pragma unroll
    for (int nt = 0; nt < 8; nt++)
#pragma unroll
        for (int e = 0; e < 4; e++) { accM0[nt][e] = 0.f; accM1[nt][e] = 0.f; }

    const int NT = K / 32;
    load_stage(0);
    CPA_COMMIT();

    for (int t = 0; t < NT; t++) {
        CPA_WAIT0();
        __syncthreads();
        if (t + 1 < NT) { load_stage(t + 1); CPA_COMMIT(); }

        const uint32_t stg  = smem_b + (t & 1) * STAGE_B;
        const uint32_t uAhi = stg;
        const uint32_t uAlo = stg + A_T_B;
        const uint32_t uBhi = stg + 2 * A_T_B;
        const uint32_t uBlo = uBhi + B_T_B;
#pragma unroll
        for (int ks = 0; ks < 2; ks++) {
            const int k0 = ks * 16;
            // ---- issue ALL 12 ldmatrix back-to-back ----
            uint32_t afh0[4], afl0[4], afh1[4], afl1[4];
            uint32_t bh[4][4], bl[4][4];
            {
                const int row0 = wm * 32 + (lane & 15);
                const int col = k0 + ((lane >> 4) << 3);
                const uint32_t off0 = (uint32_t)(row0 * SA + col) * 2;
                const uint32_t off1 = (uint32_t)((row0 + 16) * SA + col) * 2;
                ldsm_x4(afh0[0], afh0[1], afh0[2], afh0[3], uAhi + off0);
                ldsm_x4(afh1[0], afh1[1], afh1[2], afh1[3], uAhi + off1);
                ldsm_x4(afl0[0], afl0[1], afl0[2], afl0[3], uAlo + off0);
                ldsm_x4(afl1[0], afl1[1], afl1[2], afl1[3], uAlo + off1);
            }
#pragma unroll
            for (int g = 0; g < 4; g++) {
                const int row = k0 + (lane & 15);
                const int col = wn * 64 + g * 16 + ((lane >> 4) << 3);
                const uint32_t off = (uint32_t)(row * SB + col) * 2;
                ldsm_x4t(bh[g][0], bh[g][1], bh[g][2], bh[g][3], uBhi + off);
                ldsm_x4t(bl[g][0], bl[g][1], bl[g][2], bl[g][3], uBlo + off);
            }
            // ---- 48 MMAs, no interleaved loads ----
#pragma unroll
            for (int g = 0; g < 4; g++) {
                mma16816(accM0[2 * g],     afh0, &bh[g][0]);
                mma16816(accM0[2 * g + 1], afh0, &bh[g][2]);
                mma16816(accM1[2 * g],     afh1, &bh[g][0]);
                mma16816(accM1[2 * g + 1], afh1, &bh[g][2]);
                mma16816(accM0[2 * g],     afh0, &bl[g][0]);
                mma16816(accM0[2 * g + 1], afh0, &bl[g][2]);
                mma16816(accM1[2 * g],     afh1, &bl[g][0]);
                mma16816(accM1[2 * g + 1], afh1, &bl[g][2]);
                mma16816(accM0[2 * g],     afl0, &bh[g][0]);
                mma16816(accM0[2 * g + 1], afl0, &bh[g][2]);
                mma16816(accM1[2 * g],     afl1, &bh[g][0]);
                mma16816(accM1[2 * g + 1], afl1, &bh[g][2]);
            }
        }
    }

    // ---- epilogue ----
    const int group = lane >> 2;
    const int tq = lane & 3;
#pragma unroll
    for (int mt = 0; mt < 2; mt++) {
#pragma unroll
        for (int nt = 0; nt < 8; nt++) {
            float* a = (mt == 0) ? accM0[nt] : accM1[nt];
            const int row = bm + wm * 32 + mt * 16 + group;
            const int col = bn + wn * 64 + nt * 8 + tq * 2;
            if (WRITE_BF16) {
                uint32_t ph, pl;
                pack_hilo(a[0], a[1], ph, pl);
                *(uint32_t*)(Ch + (ull)row * N + col) = ph;
                *(uint32_t*)(Cl + (ull)row * N + col) = pl;
                pack_hilo(a[2], a[3], ph, pl);
                *(uint32_t*)(Ch + (ull)(row + 8) * N + col) = ph;
                *(uint32_t*)(Cl + (ull)(row + 8) * N + col) = pl;
            } else {
                *(float2*)&Cf[(ull)row * N + col] = make_float2(a[0], a[1]);
                *(float2*)&Cf[(ull)(row + 8) * N + col] = make_float2(a[2], a[3]);
            }
        }
    }
}

// ---------------------------------------------------------------------------
// HMMA flash attention, BQ=128 (R8, validated): 8 warps x 16 q-rows x 64 keys.
// ---------------------------------------------------------------------------
#define QSTR 72
#define Q_BUF 18432
#define OFF_QH 0
#define OFF_QL Q_BUF
#define KV_BASE (2 * Q_BUF)
#define KV_BUF 9216
#define KV_STAGE (4 * KV_BUF)
#define OFF_BIAS (KV_BASE + 2 * KV_STAGE)
#define ATT_SMEM (OFF_BIAS + 512)

__global__ __launch_bounds__(256, 2)
void attn_mma(const u16* __restrict__ qkvh, const u16* __restrict__ qkvl,
              const float* __restrict__ rel_bias,
              u16* __restrict__ ath, u16* __restrict__ atl) {
    extern __shared__ char sm[];
    const uint32_t sb = smem_u32(sm);
    const int tid  = threadIdx.x;
    const int lane = tid & 31;
    const int wm   = tid >> 5;
    const int h  = blockIdx.y;
    const int q0 = blockIdx.x * 128;

    float* bias_s = (float*)(sm + OFF_BIAS);
    if (tid < MAXD) bias_s[tid] = rel_bias[tid * NH + h];

    auto load_kv = [&](int kt) {
        const uint32_t sK = sb + KV_BASE + (kt & 1) * KV_STAGE;
        const ull base = (ull)(kt * 64) * TDM + h * DH;
#pragma unroll
        for (int i = 0; i < 2; i++) {
            const int c = tid + i * 256;
            const int row = c >> 3, cc = c & 7;
            const ull so = base + (ull)row * TDM + cc * 8;
            const uint32_t d = row * 144 + cc * 16;
            cpa16(sK + d,              qkvh + so + DM);
            cpa16(sK + KV_BUF + d,     qkvl + so + DM);
            cpa16(sK + 2 * KV_BUF + d, qkvh + so + 2 * DM);
            cpa16(sK + 3 * KV_BUF + d, qkvl + so + 2 * DM);
        }
    };

#pragma unroll
    for (int i = 0; i < 4; i++) {
        const int c = tid + i * 256;
        const int row = c >> 3, cc = c & 7;
        const ull so = (ull)(q0 + row) * TDM + h * DH + cc * 8;
        const uint32_t d = row * 144 + cc * 16;
        cpa16(sb + OFF_QH + d, qkvh + so);
        cpa16(sb + OFF_QL + d, qkvl + so);
    }
    load_kv(0);
    CPA_COMMIT();

    float m_a = -1e30f, m_b = -1e30f, l_a = 0.f, l_b = 0.f;
    float accO[8][4];
#pragma unroll
    for (int d = 0; d < 8; d++)
#pragma unroll
        for (int e = 0; e < 4; e++) accO[d][e] = 0.f;

    const int qa_row  = wm * 16 + (lane & 15);
    const int qa_coff = (lane >> 4) << 3;
    const int kb_key  = ((lane >> 4) << 3) + (lane & 7);
    const int kb_coff = ((lane >> 3) & 1) << 3;
    const int vb_key  = lane & 15;
    const int vb_coff = (lane >> 4) << 3;
    const int rA = wm * 16 + (lane >> 2);
    const int rB = rA + 8;
    const int qA = q0 + rA, qB = q0 + rB;

    for (int kt = 0; kt < SEQ / 64; kt++) {
        CPA_WAIT0();
        __syncthreads();
        if (kt + 1 < SEQ / 64) { load_kv(kt + 1); CPA_COMMIT(); }

        const uint32_t uKH = sb + KV_BASE + (kt & 1) * KV_STAGE;
        const uint32_t uKL = uKH + KV_BUF;
        const uint32_t uVH = uKH + 2 * KV_BUF;
        const uint32_t uVL = uKH + 3 * KV_BUF;

        float sS[8][4];
#pragma unroll
        for (int f = 0; f < 8; f++)
#pragma unroll
            for (int e = 0; e < 4; e++) sS[f][e] = 0.f;

#pragma unroll
        for (int ks = 0; ks < 4; ks++) {
            const uint32_t qoff = (uint32_t)(qa_row * QSTR + ks * 16 + qa_coff) * 2;
            uint32_t qh[4], ql[4];
            ldsm_x4(qh[0], qh[1], qh[2], qh[3], sb + OFF_QH + qoff);
            ldsm_x4(ql[0], ql[1], ql[2], ql[3], sb + OFF_QL + qoff);
#pragma unroll
            for (int kg = 0; kg < 2; kg++) {
                const uint32_t koff0 =
                    (uint32_t)((kb_key + kg * 32) * QSTR + ks * 16 + kb_coff) * 2;
                const uint32_t koff1 =
                    (uint32_t)((kb_key + kg * 32 + 16) * QSTR + ks * 16 + kb_coff) * 2;
                uint32_t kh0[4], kl0[4], kh1[4], kl1[4];
                ldsm_x4(kh0[0], kh0[1], kh0[2], kh0[3], uKH + koff0);
                ldsm_x4(kl0[0], kl0[1], kl0[2], kl0[3], uKL + koff0);
                ldsm_x4(kh1[0], kh1[1], kh1[2], kh1[3], uKH + koff1);
                ldsm_x4(kl1[0], kl1[1], kl1[2], kl1[3], uKL + koff1);
                float* s0 = sS[4 * kg + 0];
                float* s1 = sS[4 * kg + 1];
                float* s2 = sS[4 * kg + 2];
                float* s3 = sS[4 * kg + 3];
                mma16816(s0, qh, &kh0[0]);
                mma16816(s1, qh, &kh0[2]);
                mma16816(s2, qh, &kh1[0]);
                mma16816(s3, qh, &kh1[2]);
                mma16816(s0, qh, &kl0[0]);
                mma16816(s1, qh, &kl0[2]);
                mma16816(s2, qh, &kl1[0]);
                mma16816(s3, qh, &kl1[2]);
                mma16816(s0, ql, &kh0[0]);
                mma16816(s1, ql, &kh0[2]);
                mma16816(s2, ql, &kh1[0]);
                mma16816(s3, ql, &kh1[2]);
            }
        }

        const int kbase = kt * 64 + (lane & 3) * 2;
#pragma unroll
        for (int f = 0; f < 8; f++) {
#pragma unroll
            for (int e = 0; e < 2; e++) {
                const int kg = kbase + f * 8 + e;
                int dA = kg - qA; dA = dA < 0 ? -dA : dA; if (dA > MAXD - 1) dA = MAXD - 1;
                int dB = kg - qB; dB = dB < 0 ? -dB : dB; if (dB > MAXD - 1) dB = MAXD - 1;
                sS[f][e]     = fmaf(sS[f][e],     0.125f, bias_s[dA]);
                sS[f][2 + e] = fmaf(sS[f][2 + e], 0.125f, bias_s[dB]);
            }
        }

        float mxA = -1e30f, mxB = -1e30f;
#pragma unroll
        for (int f = 0; f < 8; f++) {
            mxA = fmaxf(mxA, fmaxf(sS[f][0], sS[f][1]));
            mxB = fmaxf(mxB, fmaxf(sS[f][2], sS[f][3]));
        }
        mxA = fmaxf(mxA, __shfl_xor_sync(0xffffffffu, mxA, 1));
        mxA = fmaxf(mxA, __shfl_xor_sync(0xffffffffu, mxA, 2));
        mxB = fmaxf(mxB, __shfl_xor_sync(0xffffffffu, mxB, 1));
        mxB = fmaxf(mxB, __shfl_xor_sync(0xffffffffu, mxB, 2));

        const float mnA = fmaxf(m_a, mxA), mnB = fmaxf(m_b, mxB);
        const float facA = __expf(m_a - mnA), facB = __expf(m_b - mnB);
        m_a = mnA; m_b = mnB;

        float sumA = 0.f, sumB = 0.f;
#pragma unroll
        for (int f = 0; f < 8; f++) {
#pragma unroll
            for (int e = 0; e < 2; e++) {
                sS[f][e]     = __expf(sS[f][e]     - m_a); sumA += sS[f][e];
                sS[f][2 + e] = __expf(sS[f][2 + e] - m_b); sumB += sS[f][2 + e];
            }
        }
        sumA += __shfl_xor_sync(0xffffffffu, sumA, 1);
        sumA += __shfl_xor_sync(0xffffffffu, sumA, 2);
        sumB += __shfl_xor_sync(0xffffffffu, sumB, 1);
        sumB += __shfl_xor_sync(0xffffffffu, sumB, 2);
        l_a = l_a * facA + sumA;
        l_b = l_b * facB + sumB;

#pragma unroll
        for (int d = 0; d < 8; d++) {
            accO[d][0] *= facA; accO[d][1] *= facA;
            accO[d][2] *= facB; accO[d][3] *= facB;
        }

#pragma unroll
        for (int ks2 = 0; ks2 < 4; ks2++) {
            uint32_t aH[4], aL[4];
            pack_hilo(sS[2 * ks2][0],     sS[2 * ks2][1],     aH[0], aL[0]);
            pack_hilo(sS[2 * ks2][2],     sS[2 * ks2][3],     aH[1], aL[1]);
            pack_hilo(sS[2 * ks2 + 1][0], sS[2 * ks2 + 1][1], aH[2], aL[2]);
            pack_hilo(sS[2 * ks2 + 1][2], sS[2 * ks2 + 1][3], aH[3], aL[3]);
            const int vrow = vb_key + ks2 * 16;
#pragma unroll
            for (int dp = 0; dp < 2; dp++) {
                const uint32_t voff0 =
                    (uint32_t)(vrow * QSTR + (2 * dp) * 16 + vb_coff) * 2;
                const uint32_t voff1 =
                    (uint32_t)(vrow * QSTR + (2 * dp + 1) * 16 + vb_coff) * 2;
                uint32_t vh0[4], vl0[4], vh1[4], vl1[4];
                ldsm_x4t(vh0[0], vh0[1], vh0[2], vh0[3], uVH + voff0);
                ldsm_x4t(vl0[0], vl0[1], vl0[2], vl0[3], uVL + voff0);
                ldsm_x4t(vh1[0], vh1[1], vh1[2], vh1[3], uVH + voff1);
                ldsm_x4t(vl1[0], vl1[1], vl1[2], vl1[3], uVL + voff1);
                mma16816(accO[4 * dp],     aH, &vh0[0]);
                mma16816(accO[4 * dp + 1], aH, &vh0[2]);
                mma16816(accO[4 * dp + 2], aH, &vh1[0]);
                mma16816(accO[4 * dp + 3], aH, &vh1[2]);
                mma16816(accO[4 * dp],     aH, &vl0[0]);
                mma16816(accO[4 * dp + 1], aH, &vl0[2]);
                mma16816(accO[4 * dp + 2], aH, &vl1[0]);
                mma16816(accO[4 * dp + 3], aH, &vl1[2]);
                mma16816(accO[4 * dp],     aL, &vh0[0]);
                mma16816(accO[4 * dp + 1], aL, &vh0[2]);
                mma16816(accO[4 * dp + 2], aL, &vh1[0]);
                mma16816(accO[4 * dp + 3], aL, &vh1[2]);
            }
        }
    }

    const float invA = 1.f / l_a, invB = 1.f / l_b;
    const int ecol = (lane & 3) * 2;
#pragma unroll
    for (int d = 0; d < 8; d++) {
        uint32_t ph, pl;
        pack_hilo(accO[d][0] * invA, accO[d][1] * invA, ph, pl);
        *(uint32_t*)(ath + (ull)qA * DM + h * DH + d * 8 + ecol) = ph;
        *(uint32_t*)(atl + (ull)qA * DM + h * DH + d * 8 + ecol) = pl;
        pack_hilo(accO[d][2] * invB, accO[d][3] * invB, ph, pl);
        *(uint32_t*)(ath + (ull)qB * DM + h * DH + d * 8 + ecol) = ph;
        *(uint32_t*)(atl + (ull)qB * DM + h * DH + d * 8 + ecol) = pl;
    }
}

// ---------------------------------------------------------------------------
extern "C" void kernel_launch(void* const* d_in, const int* in_sizes, int n_in,
                              void* d_out, int out_size) {
    const float* x        = (const float*)d_in[0];
    const float* w_qkv    = (const float*)d_in[1];
    const float* w_out    = (const float*)d_in[2];
    const float* rel_bias = (const float*)d_in[3];
    float* out = (float*)d_out;

    u16 *xh, *xl, *wqh, *wql, *woh, *wol, *qkvh, *qkvl, *ath, *atl;
    cudaGetSymbolAddress((void**)&xh,   g_xh);
    cudaGetSymbolAddress((void**)&xl,   g_xl);
    cudaGetSymbolAddress((void**)&wqh,  g_wqh);
    cudaGetSymbolAddress((void**)&wql,  g_wql);
    cudaGetSymbolAddress((void**)&woh,  g_woh);
    cudaGetSymbolAddress((void**)&wol,  g_wol);
    cudaGetSymbolAddress((void**)&qkvh, g_qkvh);
    cudaGetSymbolAddress((void**)&qkvl, g_qkvl);
    cudaGetSymbolAddress((void**)&ath,  g_ath);
    cudaGetSymbolAddress((void**)&atl,  g_atl);

    cudaFuncSetAttribute(gemm_bf16_v2<true>,  cudaFuncAttributeMaxDynamicSharedMemorySize, GSMEM);
    cudaFuncSetAttribute(gemm_bf16_v2<false>, cudaFuncAttributeMaxDynamicSharedMemorySize, GSMEM);
    cudaFuncSetAttribute(attn_mma, cudaFuncAttributeMaxDynamicSharedMemorySize, ATT_SMEM);

    // 0) one-time splits
    conv_split<<<(SEQ * DM / 4 + 255) / 256, 256>>>(x, xh, xl, SEQ * DM);
    conv_split<<<(DM * TDM / 4 + 255) / 256, 256>>>(w_qkv, wqh, wql, DM * TDM);
    conv_split<<<(DM * DM / 4 + 255) / 256, 256>>>(w_out, woh, wol, DM * DM);

    // 1) qkv = x @ w_qkv  -> bf16 hi/lo
    gemm_bf16_v2<true><<<dim3(TDM / 128, SEQ / 64), 128, GSMEM>>>(
        xh, xl, wqh, wql, nullptr, qkvh, qkvl, SEQ, TDM, DM);

    // 2) attention (BQ=128, warp-owns-row) -> bf16 hi/lo
    attn_mma<<<dim3(SEQ / 128, NH), 256, ATT_SMEM>>>(qkvh, qkvl, rel_bias, ath, atl);

    // 3) out = attn @ w_out -> fp32
    gemm_bf16_v2<false><<<dim3(DM / 128, SEQ / 64), 128, GSMEM>>>(
        ath, atl, woh, wol, out, nullptr, nullptr, SEQ, DM, DM);
}

// round 14
// speedup vs baseline: 1.0088x; 1.0088x over previous
#include <cuda_runtime.h>
#include <cuda_bf16.h>
#include <cstdint>
#include <math.h>

#define SEQ  2048
#define DM   1024
#define TDM  3072
#define NH   16
#define DH   64
#define MAXD 128

typedef unsigned long long ull;
typedef unsigned short u16;

// ---------------- persistent scratch (bf16 hi/lo split form) ----------------
__device__ u16 g_xh[SEQ * DM],  g_xl[SEQ * DM];
__device__ u16 g_wqh[DM * TDM], g_wql[DM * TDM];
__device__ u16 g_woh[DM * DM],  g_wol[DM * DM];
__device__ u16 g_qkvh[SEQ * TDM], g_qkvl[SEQ * TDM];
__device__ u16 g_ath[SEQ * DM],   g_atl[SEQ * DM];

// ---------------- helpers ---------------------------------------------------
__device__ __forceinline__ uint32_t smem_u32(const void* p) {
    uint32_t a;
    asm("{ .reg .u64 t; cvta.to.shared.u64 t, %1; cvt.u32.u64 %0, t; }" : "=r"(a) : "l"(p));
    return a;
}
__device__ __forceinline__ void cpa16(uint32_t dst, const void* src) {
    asm volatile("cp.async.cg.shared.global [%0], [%1], 16;" :: "r"(dst), "l"(src));
}
#define CPA_COMMIT() asm volatile("cp.async.commit_group;" ::: "memory")
#define CPA_WAIT0()  asm volatile("cp.async.wait_group 0;" ::: "memory")

__device__ __forceinline__ void ldsm_x4(uint32_t& r0, uint32_t& r1, uint32_t& r2,
                                        uint32_t& r3, uint32_t addr) {
    asm volatile("ldmatrix.sync.aligned.m8n8.x4.shared.b16 {%0,%1,%2,%3}, [%4];"
                 : "=r"(r0), "=r"(r1), "=r"(r2), "=r"(r3) : "r"(addr));
}
__device__ __forceinline__ void ldsm_x4t(uint32_t& r0, uint32_t& r1, uint32_t& r2,
                                         uint32_t& r3, uint32_t addr) {
    asm volatile("ldmatrix.sync.aligned.m8n8.x4.trans.shared.b16 {%0,%1,%2,%3}, [%4];"
                 : "=r"(r0), "=r"(r1), "=r"(r2), "=r"(r3) : "r"(addr));
}
__device__ __forceinline__ void mma16816(float* d, const uint32_t* a, const uint32_t* b) {
    asm volatile("mma.sync.aligned.m16n8k16.row.col.f32.bf16.bf16.f32 "
                 "{%0,%1,%2,%3}, {%4,%5,%6,%7}, {%8,%9}, {%0,%1,%2,%3};"
                 : "+f"(d[0]), "+f"(d[1]), "+f"(d[2]), "+f"(d[3])
                 : "r"(a[0]), "r"(a[1]), "r"(a[2]), "r"(a[3]), "r"(b[0]), "r"(b[1]));
}
__device__ __forceinline__ uint32_t bf16x2_of(float lo, float hi) {
    uint32_t r;
    asm("cvt.rn.bf16x2.f32 %0, %1, %2;" : "=r"(r) : "f"(hi), "f"(lo));
    return r;
}
__device__ __forceinline__ void pack_hilo(float x, float y, uint32_t& ph, uint32_t& pl) {
    __nv_bfloat16 hx = __float2bfloat16_rn(x);
    __nv_bfloat16 hy = __float2bfloat16_rn(y);
    float fx = __bfloat162float(hx), fy = __bfloat162float(hy);
    ph = ((uint32_t)__bfloat16_as_ushort(hy) << 16) | (uint32_t)__bfloat16_as_ushort(hx);
    pl = bf16x2_of(x - fx, y - fy);
}

// ---------------------------------------------------------------------------
// One-time fp32 -> (hi,lo) bf16 split.
// ---------------------------------------------------------------------------
__global__ __launch_bounds__(256)
void conv_split(const float* __restrict__ src, u16* __restrict__ hi,
                u16* __restrict__ lo, int n) {
    int i = (blockIdx.x * 256 + threadIdx.x) * 4;
    if (i < n) {
        float4 v = *(const float4*)(src + i);
        uint32_t h0, l0, h1, l1;
        pack_hilo(v.x, v.y, h0, l0);
        pack_hilo(v.z, v.w, h1, l1);
        *(uint32_t*)(hi + i)     = h0;
        *(uint32_t*)(hi + i + 2) = h1;
        *(uint32_t*)(lo + i)     = l0;
        *(uint32_t*)(lo + i + 2) = l1;
    }
}

// ---------------------------------------------------------------------------
// Pure-bf16 split GEMM, PERSISTENT CTAs: C = A @ B, pre-split inputs.
// CTA computes a sequence of 64x128 tiles (tile loop kills wave quantization).
// 128 threads = 4 warps (2 wm x 2 wn), warp tile 32x64. R10 interleaved inner.
// ---------------------------------------------------------------------------
#define SA 40
#define SB 136
#define A_T_B 5120
#define B_T_B 8704
#define STAGE_B (2 * A_T_B + 2 * B_T_B)   // 27648
#define GSMEM   (2 * STAGE_B)             // 55296
#define PERSIST_CTAS 592                  // 148 SMs x 4 CTAs

template <bool WRITE_BF16>
__global__ __launch_bounds__(128, 4)
void gemm_bf16_v2(const u16* __restrict__ Ah, const u16* __restrict__ Al,
                  const u16* __restrict__ Bh, const u16* __restrict__ Bl,
                  float* __restrict__ Cf, u16* __restrict__ Ch, u16* __restrict__ Cl,
                  int M, int N, int K, int ntx, int numTiles) {
    extern __shared__ char smem[];
    const uint32_t smem_b = smem_u32(smem);
    const int tid  = threadIdx.x;
    const int lane = tid & 31;
    const int wid  = tid >> 5;
    const int wm   = wid & 1;
    const int wn   = wid >> 1;
    const int NT = K / 32;

    for (int tile = blockIdx.x; tile < numTiles; tile += gridDim.x) {
        const int bm = (tile / ntx) * 64;
        const int bn = (tile % ntx) * 128;

        auto load_stage = [&](int t) {
            const uint32_t stg = smem_b + (t & 1) * STAGE_B;
#pragma unroll
            for (int i = 0; i < 2; i++) {
                const int c = tid + i * 128;
                const int row = c >> 2, cc = c & 3;
                const ull sa = (ull)(bm + row) * K + t * 32 + cc * 8;
                cpa16(stg + row * 80 + cc * 16,         Ah + sa);
                cpa16(stg + A_T_B + row * 80 + cc * 16, Al + sa);
            }
#pragma unroll
            for (int i = 0; i < 4; i++) {
                const int c = tid + i * 128;
                const int rb = c >> 4, cb = c & 15;
                const ull sbp = (ull)(t * 32 + rb) * N + bn + cb * 8;
                cpa16(stg + 2 * A_T_B + rb * 272 + cb * 16,         Bh + sbp);
                cpa16(stg + 2 * A_T_B + B_T_B + rb * 272 + cb * 16, Bl + sbp);
            }
        };

        float accM0[8][4], accM1[8][4];
#pragma unroll
        for (int nt = 0; nt < 8; nt++)
#pragma unroll
            for (int e = 0; e < 4; e++) { accM0[nt][e] = 0.f; accM1[nt][e] = 0.f; }

        load_stage(0);
        CPA_COMMIT();

        for (int t = 0; t < NT; t++) {
            CPA_WAIT0();
            __syncthreads();
            if (t + 1 < NT) { load_stage(t + 1); CPA_COMMIT(); }

            const uint32_t stg  = smem_b + (t & 1) * STAGE_B;
            const uint32_t uAhi = stg;
            const uint32_t uAlo = stg + A_T_B;
            const uint32_t uBhi = stg + 2 * A_T_B;
            const uint32_t uBlo = uBhi + B_T_B;
#pragma unroll
            for (int ks = 0; ks < 2; ks++) {
                const int k0 = ks * 16;
                uint32_t afh0[4], afl0[4], afh1[4], afl1[4];
                {
                    const int row0 = wm * 32 + (lane & 15);
                    const int col = k0 + ((lane >> 4) << 3);
                    const uint32_t off0 = (uint32_t)(row0 * SA + col) * 2;
                    const uint32_t off1 = (uint32_t)((row0 + 16) * SA + col) * 2;
                    ldsm_x4(afh0[0], afh0[1], afh0[2], afh0[3], uAhi + off0);
                    ldsm_x4(afl0[0], afl0[1], afl0[2], afl0[3], uAlo + off0);
                    ldsm_x4(afh1[0], afh1[1], afh1[2], afh1[3], uAhi + off1);
                    ldsm_x4(afl1[0], afl1[1], afl1[2], afl1[3], uAlo + off1);
                }
#pragma unroll
                for (int g = 0; g < 4; g++) {
                    uint32_t bh[4], bl[4];
                    const int row = k0 + (lane & 15);
                    const int col = wn * 64 + g * 16 + ((lane >> 4) << 3);
                    const uint32_t off = (uint32_t)(row * SB + col) * 2;
                    ldsm_x4t(bh[0], bh[1], bh[2], bh[3], uBhi + off);
                    ldsm_x4t(bl[0], bl[1], bl[2], bl[3], uBlo + off);
                    // hh
                    mma16816(accM0[2 * g],     afh0, &bh[0]);
                    mma16816(accM0[2 * g + 1], afh0, &bh[2]);
                    mma16816(accM1[2 * g],     afh1, &bh[0]);
                    mma16816(accM1[2 * g + 1], afh1, &bh[2]);
                    // hl
                    mma16816(accM0[2 * g],     afh0, &bl[0]);
                    mma16816(accM0[2 * g + 1], afh0, &bl[2]);
                    mma16816(accM1[2 * g],     afh1, &bl[0]);
                    mma16816(accM1[2 * g + 1], afh1, &bl[2]);
                    // lh
                    mma16816(accM0[2 * g],     afl0, &bh[0]);
                    mma16816(accM0[2 * g + 1], afl0, &bh[2]);
                    mma16816(accM1[2 * g],     afl1, &bh[0]);
                    mma16816(accM1[2 * g + 1], afl1, &bh[2]);
                }
            }
        }

        // ---- epilogue ----
        const int group = lane >> 2;
        const int tq = lane & 3;
#pragma unroll
        for (int mt = 0; mt < 2; mt++) {
#pragma unroll
            for (int nt = 0; nt < 8; nt++) {
                float* a = (mt == 0) ? accM0[nt] : accM1[nt];
                const int row = bm + wm * 32 + mt * 16 + group;
                const int col = bn + wn * 64 + nt * 8 + tq * 2;
                if (WRITE_BF16) {
                    uint32_t ph, pl;
                    pack_hilo(a[0], a[1], ph, pl);
                    *(uint32_t*)(Ch + (ull)row * N + col) = ph;
                    *(uint32_t*)(Cl + (ull)row * N + col) = pl;
                    pack_hilo(a[2], a[3], ph, pl);
                    *(uint32_t*)(Ch + (ull)(row + 8) * N + col) = ph;
                    *(uint32_t*)(Cl + (ull)(row + 8) * N + col) = pl;
                } else {
                    *(float2*)&Cf[(ull)row * N + col] = make_float2(a[0], a[1]);
                    *(float2*)&Cf[(ull)(row + 8) * N + col] = make_float2(a[2], a[3]);
                }
            }
        }
    }
}

// ---------------------------------------------------------------------------
// HMMA flash attention, BQ=128 (R8, validated): 8 warps x 16 q-rows x 64 keys.
// ---------------------------------------------------------------------------
#define QSTR 72
#define Q_BUF 18432
#define OFF_QH 0
#define OFF_QL Q_BUF
#define KV_BASE (2 * Q_BUF)
#define KV_BUF 9216
#define KV_STAGE (4 * KV_BUF)
#define OFF_BIAS (KV_BASE + 2 * KV_STAGE)
#define ATT_SMEM (OFF_BIAS + 512)

__global__ __launch_bounds__(256, 2)
void attn_mma(const u16* __restrict__ qkvh, const u16* __restrict__ qkvl,
              const float* __restrict__ rel_bias,
              u16* __restrict__ ath, u16* __restrict__ atl) {
    extern __shared__ char sm[];
    const uint32_t sb = smem_u32(sm);
    const int tid  = threadIdx.x;
    const int lane = tid & 31;
    const int wm   = tid >> 5;
    const int h  = blockIdx.y;
    const int q0 = blockIdx.x * 128;

    float* bias_s = (float*)(sm + OFF_BIAS);
    if (tid < MAXD) bias_s[tid] = rel_bias[tid * NH + h];

    auto load_kv = [&](int kt) {
        const uint32_t sK = sb + KV_BASE + (kt & 1) * KV_STAGE;
        const ull base = (ull)(kt * 64) * TDM + h * DH;
#pragma unroll
        for (int i = 0; i < 2; i++) {
            const int c = tid + i * 256;
            const int row = c >> 3, cc = c & 7;
            const ull so = base + (ull)row * TDM + cc * 8;
            const uint32_t d = row * 144 + cc * 16;
            cpa16(sK + d,              qkvh + so + DM);
            cpa16(sK + KV_BUF + d,     qkvl + so + DM);
            cpa16(sK + 2 * KV_BUF + d, qkvh + so + 2 * DM);
            cpa16(sK + 3 * KV_BUF + d, qkvl + so + 2 * DM);
        }
    };

#pragma unroll
    for (int i = 0; i < 4; i++) {
        const int c = tid + i * 256;
        const int row = c >> 3, cc = c & 7;
        const ull so = (ull)(q0 + row) * TDM + h * DH + cc * 8;
        const uint32_t d = row * 144 + cc * 16;
        cpa16(sb + OFF_QH + d, qkvh + so);
        cpa16(sb + OFF_QL + d, qkvl + so);
    }
    load_kv(0);
    CPA_COMMIT();

    float m_a = -1e30f, m_b = -1e30f, l_a = 0.f, l_b = 0.f;
    float accO[8][4];
#pragma unroll
    for (int d = 0; d < 8; d++)
#pragma unroll
        for (int e = 0; e < 4; e++) accO[d][e] = 0.f;

    const int qa_row  = wm * 16 + (lane & 15);
    const int qa_coff = (lane >> 4) << 3;
    const int kb_key  = ((lane >> 4) << 3) + (lane & 7);
    const int kb_coff = ((lane >> 3) & 1) << 3;
    const int vb_key  = lane & 15;
    const int vb_coff = (lane >> 4) << 3;
    const int rA = wm * 16 + (lane >> 2);
    const int rB = rA + 8;
    const int qA = q0 + rA, qB = q0 + rB;

    for (int kt = 0; kt < SEQ / 64; kt++) {
        CPA_WAIT0();
        __syncthreads();
        if (kt + 1 < SEQ / 64) { load_kv(kt + 1); CPA_COMMIT(); }

        const uint32_t uKH = sb + KV_BASE + (kt & 1) * KV_STAGE;
        const uint32_t uKL = uKH + KV_BUF;
        const uint32_t uVH = uKH + 2 * KV_BUF;
        const uint32_t uVL = uKH + 3 * KV_BUF;

        float sS[8][4];
#pragma unroll
        for (int f = 0; f < 8; f++)
#pragma unroll
            for (int e = 0; e < 4; e++) sS[f][e] = 0.f;

#pragma unroll
        for (int ks = 0; ks < 4; ks++) {
            const uint32_t qoff = (uint32_t)(qa_row * QSTR + ks * 16 + qa_coff) * 2;
            uint32_t qh[4], ql[4];
            ldsm_x4(qh[0], qh[1], qh[2], qh[3], sb + OFF_QH + qoff);
            ldsm_x4(ql[0], ql[1], ql[2], ql[3], sb + OFF_QL + qoff);
#pragma unroll
            for (int kg = 0; kg < 2; kg++) {
                const uint32_t koff0 =
                    (uint32_t)((kb_key + kg * 32) * QSTR + ks * 16 + kb_coff) * 2;
                const uint32_t koff1 =
                    (uint32_t)((kb_key + kg * 32 + 16) * QSTR + ks * 16 + kb_coff) * 2;
                uint32_t kh0[4], kl0[4], kh1[4], kl1[4];
                ldsm_x4(kh0[0], kh0[1], kh0[2], kh0[3], uKH + koff0);
                ldsm_x4(kl0[0], kl0[1], kl0[2], kl0[3], uKL + koff0);
                ldsm_x4(kh1[0], kh1[1], kh1[2], kh1[3], uKH + koff1);
                ldsm_x4(kl1[0], kl1[1], kl1[2], kl1[3], uKL + koff1);
                float* s0 = sS[4 * kg + 0];
                float* s1 = sS[4 * kg + 1];
                float* s2 = sS[4 * kg + 2];
                float* s3 = sS[4 * kg + 3];
                mma16816(s0, qh, &kh0[0]);
                mma16816(s1, qh, &kh0[2]);
                mma16816(s2, qh, &kh1[0]);
                mma16816(s3, qh, &kh1[2]);
                mma16816(s0, qh, &kl0[0]);
                mma16816(s1, qh, &kl0[2]);
                mma16816(s2, qh, &kl1[0]);
                mma16816(s3, qh, &kl1[2]);
                mma16816(s0, ql, &kh0[0]);
                mma16816(s1, ql, &kh0[2]);
                mma16816(s2, ql, &kh1[0]);
                mma16816(s3, ql, &kh1[2]);
            }
        }

        const int kbase = kt * 64 + (lane & 3) * 2;
#pragma unroll
        for (int f = 0; f < 8; f++) {
#pragma unroll
            for (int e = 0; e < 2; e++) {
                const int kg = kbase + f * 8 + e;
                int dA = kg - qA; dA = dA < 0 ? -dA : dA; if (dA > MAXD - 1) dA = MAXD - 1;
                int dB = kg - qB; dB = dB < 0 ? -dB : dB; if (dB > MAXD - 1) dB = MAXD - 1;
                sS[f][e]     = fmaf(sS[f][e],     0.125f, bias_s[dA]);
                sS[f][2 + e] = fmaf(sS[f][2 + e], 0.125f, bias_s[dB]);
            }
        }

        float mxA = -1e30f, mxB = -1e30f;
#pragma unroll
        for (int f = 0; f < 8; f++) {
            mxA = fmaxf(mxA, fmaxf(sS[f][0], sS[f][1]));
            mxB = fmaxf(mxB, fmaxf(sS[f][2], sS[f][3]));
        }
        mxA = fmaxf(mxA, __shfl_xor_sync(0xffffffffu, mxA, 1));
        mxA = fmaxf(mxA, __shfl_xor_sync(0xffffffffu, mxA, 2));
        mxB = fmaxf(mxB, __shfl_xor_sync(0xffffffffu, mxB, 1));
        mxB = fmaxf(mxB, __shfl_xor_sync(0xffffffffu, mxB, 2));

        const float mnA = fmaxf(m_a, mxA), mnB = fmaxf(m_b, mxB);
        const float facA = __expf(m_a - mnA), facB = __expf(m_b - mnB);
        m_a = mnA; m_b = mnB;

        float sumA = 0.f, sumB = 0.f;
#pragma unroll
        for (int f = 0; f < 8; f++) {
#pragma unroll
            for (int e = 0; e < 2; e++) {
                sS[f][e]     = __expf(sS[f][e]     - m_a); sumA += sS[f][e];
                sS[f][2 + e] = __expf(sS[f][2 + e] - m_b); sumB += sS[f][2 + e];
            }
        }
        sumA += __shfl_xor_sync(0xffffffffu, sumA, 1);
        sumA += __shfl_xor_sync(0xffffffffu, sumA, 2);
        sumB += __shfl_xor_sync(0xffffffffu, sumB, 1);
        sumB += __shfl_xor_sync(0xffffffffu, sumB, 2);
        l_a = l_a * facA + sumA;
        l_b = l_b * facB + sumB;

#pragma unroll
        for (int d = 0; d < 8; d++) {
            accO[d][0] *= facA; accO[d][1] *= facA;
            accO[d][2] *= facB; accO[d][3] *= facB;
        }

#pragma unroll
        for (int ks2 = 0; ks2 < 4; ks2++) {
            uint32_t aH[4], aL[4];
            pack_hilo(sS[2 * ks2][0],     sS[2 * ks2][1],     aH[0], aL[0]);
            pack_hilo(sS[2 * ks2][2],     sS[2 * ks2][3],     aH[1], aL[1]);
            pack_hilo(sS[2 * ks2 + 1][0], sS[2 * ks2 + 1][1], aH[2], aL[2]);
            pack_hilo(sS[2 * ks2 + 1][2], sS[2 * ks2 + 1][3], aH[3], aL[3]);
            const int vrow = vb_key + ks2 * 16;
#pragma unroll
            for (int dp = 0; dp < 2; dp++) {
                const uint32_t voff0 =
                    (uint32_t)(vrow * QSTR + (2 * dp) * 16 + vb_coff) * 2;
                const uint32_t voff1 =
                    (uint32_t)(vrow * QSTR + (2 * dp + 1) * 16 + vb_coff) * 2;
                uint32_t vh0[4], vl0[4], vh1[4], vl1[4];
                ldsm_x4t(vh0[0], vh0[1], vh0[2], vh0[3], uVH + voff0);
                ldsm_x4t(vl0[0], vl0[1], vl0[2], vl0[3], uVL + voff0);
                ldsm_x4t(vh1[0], vh1[1], vh1[2], vh1[3], uVH + voff1);
                ldsm_x4t(vl1[0], vl1[1], vl1[2], vl1[3], uVL + voff1);
                mma16816(accO[4 * dp],     aH, &vh0[0]);
                mma16816(accO[4 * dp + 1], aH, &vh0[2]);
                mma16816(accO[4 * dp + 2], aH, &vh1[0]);
                mma16816(accO[4 * dp + 3], aH, &vh1[2]);
                mma16816(accO[4 * dp],     aH, &vl0[0]);
                mma16816(accO[4 * dp + 1], aH, &vl0[2]);
                mma16816(accO[4 * dp + 2], aH, &vl1[0]);
                mma16816(accO[4 * dp + 3], aH, &vl1[2]);
                mma16816(accO[4 * dp],     aL, &vh0[0]);
                mma16816(accO[4 * dp + 1], aL, &vh0[2]);
                mma16816(accO[4 * dp + 2], aL, &vh1[0]);
                mma16816(accO[4 * dp + 3], aL, &vh1[2]);
            }
        }
    }

    const float invA = 1.f / l_a, invB = 1.f / l_b;
    const int ecol = (lane & 3) * 2;
#pragma unroll
    for (int d = 0; d < 8; d++) {
        uint32_t ph, pl;
        pack_hilo(accO[d][0] * invA, accO[d][1] * invA, ph, pl);
        *(uint32_t*)(ath + (ull)qA * DM + h * DH + d * 8 + ecol) = ph;
        *(uint32_t*)(atl + (ull)qA * DM + h * DH + d * 8 + ecol) = pl;
        pack_hilo(accO[d][2] * invB, accO[d][3] * invB, ph, pl);
        *(uint32_t*)(ath + (ull)qB * DM + h * DH + d * 8 + ecol) = ph;
        *(uint32_t*)(atl + (ull)qB * DM + h * DH + d * 8 + ecol) = pl;
    }
}

// ---------------------------------------------------------------------------
extern "C" void kernel_launch(void* const* d_in, const int* in_sizes, int n_in,
                              void* d_out, int out_size) {
    const float* x        = (const float*)d_in[0];
    const float* w_qkv    = (const float*)d_in[1];
    const float* w_out    = (const float*)d_in[2];
    const float* rel_bias = (const float*)d_in[3];
    float* out = (float*)d_out;

    u16 *xh, *xl, *wqh, *wql, *woh, *wol, *qkvh, *qkvl, *ath, *atl;
    cudaGetSymbolAddress((void**)&xh,   g_xh);
    cudaGetSymbolAddress((void**)&xl,   g_xl);
    cudaGetSymbolAddress((void**)&wqh,  g_wqh);
    cudaGetSymbolAddress((void**)&wql,  g_wql);
    cudaGetSymbolAddress((void**)&woh,  g_woh);
    cudaGetSymbolAddress((void**)&wol,  g_wol);
    cudaGetSymbolAddress((void**)&qkvh, g_qkvh);
    cudaGetSymbolAddress((void**)&qkvl, g_qkvl);
    cudaGetSymbolAddress((void**)&ath,  g_ath);
    cudaGetSymbolAddress((void**)&atl,  g_atl);

    cudaFuncSetAttribute(gemm_bf16_v2<true>,  cudaFuncAttributeMaxDynamicSharedMemorySize, GSMEM);
    cudaFuncSetAttribute(gemm_bf16_v2<false>, cudaFuncAttributeMaxDynamicSharedMemorySize, GSMEM);
    cudaFuncSetAttribute(attn_mma, cudaFuncAttributeMaxDynamicSharedMemorySize, ATT_SMEM);

    // 0) one-time splits
    conv_split<<<(SEQ * DM / 4 + 255) / 256, 256>>>(x, xh, xl, SEQ * DM);
    conv_split<<<(DM * TDM / 4 + 255) / 256, 256>>>(w_qkv, wqh, wql, DM * TDM);
    conv_split<<<(DM * DM / 4 + 255) / 256, 256>>>(w_out, woh, wol, DM * DM);

    // 1) qkv = x @ w_qkv  -> bf16 hi/lo   (persistent CTAs kill tail wave)
    {
        const int ntx = TDM / 128, nty = SEQ / 64;
        const int tiles = ntx * nty;                       // 768
        const int grid = tiles < PERSIST_CTAS ? tiles : PERSIST_CTAS;
        gemm_bf16_v2<true><<<grid, 128, GSMEM>>>(
            xh, xl, wqh, wql, nullptr, qkvh, qkvl, SEQ, TDM, DM, ntx, tiles);
    }

    // 2) attention (BQ=128, warp-owns-row) -> bf16 hi/lo
    attn_mma<<<dim3(SEQ / 128, NH), 256, ATT_SMEM>>>(qkvh, qkvl, rel_bias, ath, atl);

    // 3) out = attn @ w_out -> fp32
    {
        const int ntx = DM / 128, nty = SEQ / 64;
        const int tiles = ntx * nty;                       // 256
        const int grid = tiles < PERSIST_CTAS ? tiles : PERSIST_CTAS;
        gemm_bf16_v2<false><<<grid, 128, GSMEM>>>(
            ath, atl, woh, wol, out, nullptr, nullptr, SEQ, DM, DM, ntx, tiles);
    }
}

// round 15
// speedup vs baseline: 1.0468x; 1.0376x over previous
#include <cuda_runtime.h>
#include <cuda_bf16.h>
#include <cstdint>
#include <math.h>

#define SEQ  2048
#define DM   1024
#define TDM  3072
#define NH   16
#define DH   64
#define MAXD 128

typedef unsigned long long ull;
typedef unsigned short u16;

// ---------------- persistent scratch (bf16 hi/lo split form) ----------------
__device__ u16 g_xh[SEQ * DM],  g_xl[SEQ * DM];
__device__ u16 g_wqh[DM * TDM], g_wql[DM * TDM];
__device__ u16 g_woh[DM * DM],  g_wol[DM * DM];
__device__ u16 g_qkvh[SEQ * TDM], g_qkvl[SEQ * TDM];
__device__ u16 g_ath[SEQ * DM],   g_atl[SEQ * DM];

// ---------------- helpers ---------------------------------------------------
__device__ __forceinline__ uint32_t smem_u32(const void* p) {
    uint32_t a;
    asm("{ .reg .u64 t; cvta.to.shared.u64 t, %1; cvt.u32.u64 %0, t; }" : "=r"(a) : "l"(p));
    return a;
}
__device__ __forceinline__ void cpa16(uint32_t dst, const void* src) {
    asm volatile("cp.async.cg.shared.global [%0], [%1], 16;" :: "r"(dst), "l"(src));
}
#define CPA_COMMIT() asm volatile("cp.async.commit_group;" ::: "memory")
#define CPA_WAIT0()  asm volatile("cp.async.wait_group 0;" ::: "memory")

__device__ __forceinline__ void ldsm_x4(uint32_t& r0, uint32_t& r1, uint32_t& r2,
                                        uint32_t& r3, uint32_t addr) {
    asm volatile("ldmatrix.sync.aligned.m8n8.x4.shared.b16 {%0,%1,%2,%3}, [%4];"
                 : "=r"(r0), "=r"(r1), "=r"(r2), "=r"(r3) : "r"(addr));
}
__device__ __forceinline__ void ldsm_x4t(uint32_t& r0, uint32_t& r1, uint32_t& r2,
                                         uint32_t& r3, uint32_t addr) {
    asm volatile("ldmatrix.sync.aligned.m8n8.x4.trans.shared.b16 {%0,%1,%2,%3}, [%4];"
                 : "=r"(r0), "=r"(r1), "=r"(r2), "=r"(r3) : "r"(addr));
}
__device__ __forceinline__ void mma16816(float* d, const uint32_t* a, const uint32_t* b) {
    asm volatile("mma.sync.aligned.m16n8k16.row.col.f32.bf16.bf16.f32 "
                 "{%0,%1,%2,%3}, {%4,%5,%6,%7}, {%8,%9}, {%0,%1,%2,%3};"
                 : "+f"(d[0]), "+f"(d[1]), "+f"(d[2]), "+f"(d[3])
                 : "r"(a[0]), "r"(a[1]), "r"(a[2]), "r"(a[3]), "r"(b[0]), "r"(b[1]));
}
__device__ __forceinline__ uint32_t bf16x2_of(float lo, float hi) {
    uint32_t r;
    asm("cvt.rn.bf16x2.f32 %0, %1, %2;" : "=r"(r) : "f"(hi), "f"(lo));
    return r;
}
__device__ __forceinline__ void pack_hilo(float x, float y, uint32_t& ph, uint32_t& pl) {
    __nv_bfloat16 hx = __float2bfloat16_rn(x);
    __nv_bfloat16 hy = __float2bfloat16_rn(y);
    float fx = __bfloat162float(hx), fy = __bfloat162float(hy);
    ph = ((uint32_t)__bfloat16_as_ushort(hy) << 16) | (uint32_t)__bfloat16_as_ushort(hx);
    pl = bf16x2_of(x - fx, y - fy);
}

// ---------------------------------------------------------------------------
// One-time fp32 -> (hi,lo) bf16 split, ALL THREE tensors in one launch.
// Segment 0: x (2M elems), 1: w_qkv (3M), 2: w_out (1M).
// ---------------------------------------------------------------------------
#define NX (SEQ * DM)
#define NW (DM * TDM)
#define NO (DM * DM)

__global__ __launch_bounds__(256)
void conv_split_all(const float* __restrict__ x, const float* __restrict__ wq,
                    const float* __restrict__ wo,
                    u16* __restrict__ xh, u16* __restrict__ xl,
                    u16* __restrict__ wqh, u16* __restrict__ wql,
                    u16* __restrict__ woh, u16* __restrict__ wol) {
    int i = (blockIdx.x * 256 + threadIdx.x) * 4;
    const float* src;
    u16 *hi, *lo;
    if (i < NX) {
        src = x; hi = xh; lo = xl;
    } else if (i < NX + NW) {
        i -= NX; src = wq; hi = wqh; lo = wql;
    } else if (i < NX + NW + NO) {
        i -= NX + NW; src = wo; hi = woh; lo = wol;
    } else {
        return;
    }
    float4 v = *(const float4*)(src + i);
    uint32_t h0, l0, h1, l1;
    pack_hilo(v.x, v.y, h0, l0);
    pack_hilo(v.z, v.w, h1, l1);
    *(uint32_t*)(hi + i)     = h0;
    *(uint32_t*)(hi + i + 2) = h1;
    *(uint32_t*)(lo + i)     = l0;
    *(uint32_t*)(lo + i + 2) = l1;
}

// ---------------------------------------------------------------------------
// Pure-bf16 split GEMM (R10, best measured): C = A @ B, pre-split inputs.
// CTA 64x128, 128 threads = 4 warps (2 wm x 2 wn), warp tile 32x64.
// ---------------------------------------------------------------------------
#define SA 40
#define SB 136
#define A_T_B 5120
#define B_T_B 8704
#define STAGE_B (2 * A_T_B + 2 * B_T_B)   // 27648
#define GSMEM   (2 * STAGE_B)             // 55296

template <bool WRITE_BF16>
__global__ __launch_bounds__(128, 4)
void gemm_bf16_v2(const u16* __restrict__ Ah, const u16* __restrict__ Al,
                  const u16* __restrict__ Bh, const u16* __restrict__ Bl,
                  float* __restrict__ Cf, u16* __restrict__ Ch, u16* __restrict__ Cl,
                  int M, int N, int K) {
    extern __shared__ char smem[];
    const uint32_t smem_b = smem_u32(smem);
    const int tid  = threadIdx.x;
    const int lane = tid & 31;
    const int wid  = tid >> 5;
    const int wm   = wid & 1;
    const int wn   = wid >> 1;
    const int bm = blockIdx.y * 64;
    const int bn = blockIdx.x * 128;

    auto load_stage = [&](int t) {
        const uint32_t stg = smem_b + (t & 1) * STAGE_B;
#pragma unroll
        for (int i = 0; i < 2; i++) {
            const int c = tid + i * 128;
            const int row = c >> 2, cc = c & 3;
            const ull sa = (ull)(bm + row) * K + t * 32 + cc * 8;
            cpa16(stg + row * 80 + cc * 16,         Ah + sa);
            cpa16(stg + A_T_B + row * 80 + cc * 16, Al + sa);
        }
#pragma unroll
        for (int i = 0; i < 4; i++) {
            const int c = tid + i * 128;
            const int rb = c >> 4, cb = c & 15;
            const ull sbp = (ull)(t * 32 + rb) * N + bn + cb * 8;
            cpa16(stg + 2 * A_T_B + rb * 272 + cb * 16,         Bh + sbp);
            cpa16(stg + 2 * A_T_B + B_T_B + rb * 272 + cb * 16, Bl + sbp);
        }
    };

    float accM0[8][4], accM1[8][4];
#pragma unroll
    for (int nt = 0; nt < 8; nt++)
#pragma unroll
        for (int e = 0; e < 4; e++) { accM0[nt][e] = 0.f; accM1[nt][e] = 0.f; }

    const int NT = K / 32;
    load_stage(0);
    CPA_COMMIT();

    for (int t = 0; t < NT; t++) {
        CPA_WAIT0();
        __syncthreads();
        if (t + 1 < NT) { load_stage(t + 1); CPA_COMMIT(); }

        const uint32_t stg  = smem_b + (t & 1) * STAGE_B;
        const uint32_t uAhi = stg;
        const uint32_t uAlo = stg + A_T_B;
        const uint32_t uBhi = stg + 2 * A_T_B;
        const uint32_t uBlo = uBhi + B_T_B;
#pragma unroll
        for (int ks = 0; ks < 2; ks++) {
            const int k0 = ks * 16;
            uint32_t afh0[4], afl0[4], afh1[4], afl1[4];
            {
                const int row0 = wm * 32 + (lane & 15);
                const int col = k0 + ((lane >> 4) << 3);
                const uint32_t off0 = (uint32_t)(row0 * SA + col) * 2;
                const uint32_t off1 = (uint32_t)((row0 + 16) * SA + col) * 2;
                ldsm_x4(afh0[0], afh0[1], afh0[2], afh0[3], uAhi + off0);
                ldsm_x4(afl0[0], afl0[1], afl0[2], afl0[3], uAlo + off0);
                ldsm_x4(afh1[0], afh1[1], afh1[2], afh1[3], uAhi + off1);
                ldsm_x4(afl1[0], afl1[1], afl1[2], afl1[3], uAlo + off1);
            }
#pragma unroll
            for (int g = 0; g < 4; g++) {
                uint32_t bh[4], bl[4];
                const int row = k0 + (lane & 15);
                const int col = wn * 64 + g * 16 + ((lane >> 4) << 3);
                const uint32_t off = (uint32_t)(row * SB + col) * 2;
                ldsm_x4t(bh[0], bh[1], bh[2], bh[3], uBhi + off);
                ldsm_x4t(bl[0], bl[1], bl[2], bl[3], uBlo + off);
                // hh
                mma16816(accM0[2 * g],     afh0, &bh[0]);
                mma16816(accM0[2 * g + 1], afh0, &bh[2]);
                mma16816(accM1[2 * g],     afh1, &bh[0]);
                mma16816(accM1[2 * g + 1], afh1, &bh[2]);
                // hl
                mma16816(accM0[2 * g],     afh0, &bl[0]);
                mma16816(accM0[2 * g + 1], afh0, &bl[2]);
                mma16816(accM1[2 * g],     afh1, &bl[0]);
                mma16816(accM1[2 * g + 1], afh1, &bl[2]);
                // lh
                mma16816(accM0[2 * g],     afl0, &bh[0]);
                mma16816(accM0[2 * g + 1], afl0, &bh[2]);
                mma16816(accM1[2 * g],     afl1, &bh[0]);
                mma16816(accM1[2 * g + 1], afl1, &bh[2]);
            }
        }
    }

    // ---- epilogue ----
    const int group = lane >> 2;
    const int tq = lane & 3;
#pragma unroll
    for (int mt = 0; mt < 2; mt++) {
#pragma unroll
        for (int nt = 0; nt < 8; nt++) {
            float* a = (mt == 0) ? accM0[nt] : accM1[nt];
            const int row = bm + wm * 32 + mt * 16 + group;
            const int col = bn + wn * 64 + nt * 8 + tq * 2;
            if (WRITE_BF16) {
                uint32_t ph, pl;
                pack_hilo(a[0], a[1], ph, pl);
                *(uint32_t*)(Ch + (ull)row * N + col) = ph;
                *(uint32_t*)(Cl + (ull)row * N + col) = pl;
                pack_hilo(a[2], a[3], ph, pl);
                *(uint32_t*)(Ch + (ull)(row + 8) * N + col) = ph;
                *(uint32_t*)(Cl + (ull)(row + 8) * N + col) = pl;
            } else {
                *(float2*)&Cf[(ull)row * N + col] = make_float2(a[0], a[1]);
                *(float2*)&Cf[(ull)(row + 8) * N + col] = make_float2(a[2], a[3]);
            }
        }
    }
}

// ---------------------------------------------------------------------------
// HMMA flash attention, BQ=128 (R8, validated): 8 warps x 16 q-rows x 64 keys.
// ---------------------------------------------------------------------------
#define QSTR 72
#define Q_BUF 18432
#define OFF_QH 0
#define OFF_QL Q_BUF
#define KV_BASE (2 * Q_BUF)
#define KV_BUF 9216
#define KV_STAGE (4 * KV_BUF)
#define OFF_BIAS (KV_BASE + 2 * KV_STAGE)
#define ATT_SMEM (OFF_BIAS + 512)

__global__ __launch_bounds__(256, 2)
void attn_mma(const u16* __restrict__ qkvh, const u16* __restrict__ qkvl,
              const float* __restrict__ rel_bias,
              u16* __restrict__ ath, u16* __restrict__ atl) {
    extern __shared__ char sm[];
    const uint32_t sb = smem_u32(sm);
    const int tid  = threadIdx.x;
    const int lane = tid & 31;
    const int wm   = tid >> 5;
    const int h  = blockIdx.y;
    const int q0 = blockIdx.x * 128;

    float* bias_s = (float*)(sm + OFF_BIAS);
    if (tid < MAXD) bias_s[tid] = rel_bias[tid * NH + h];

    auto load_kv = [&](int kt) {
        const uint32_t sK = sb + KV_BASE + (kt & 1) * KV_STAGE;
        const ull base = (ull)(kt * 64) * TDM + h * DH;
#pragma unroll
        for (int i = 0; i < 2; i++) {
            const int c = tid + i * 256;
            const int row = c >> 3, cc = c & 7;
            const ull so = base + (ull)row * TDM + cc * 8;
            const uint32_t d = row * 144 + cc * 16;
            cpa16(sK + d,              qkvh + so + DM);
            cpa16(sK + KV_BUF + d,     qkvl + so + DM);
            cpa16(sK + 2 * KV_BUF + d, qkvh + so + 2 * DM);
            cpa16(sK + 3 * KV_BUF + d, qkvl + so + 2 * DM);
        }
    };

#pragma unroll
    for (int i = 0; i < 4; i++) {
        const int c = tid + i * 256;
        const int row = c >> 3, cc = c & 7;
        const ull so = (ull)(q0 + row) * TDM + h * DH + cc * 8;
        const uint32_t d = row * 144 + cc * 16;
        cpa16(sb + OFF_QH + d, qkvh + so);
        cpa16(sb + OFF_QL + d, qkvl + so);
    }
    load_kv(0);
    CPA_COMMIT();

    float m_a = -1e30f, m_b = -1e30f, l_a = 0.f, l_b = 0.f;
    float accO[8][4];
#pragma unroll
    for (int d = 0; d < 8; d++)
#pragma unroll
        for (int e = 0; e < 4; e++) accO[d][e] = 0.f;

    const int qa_row  = wm * 16 + (lane & 15);
    const int qa_coff = (lane >> 4) << 3;
    const int kb_key  = ((lane >> 4) << 3) + (lane & 7);
    const int kb_coff = ((lane >> 3) & 1) << 3;
    const int vb_key  = lane & 15;
    const int vb_coff = (lane >> 4) << 3;
    const int rA = wm * 16 + (lane >> 2);
    const int rB = rA + 8;
    const int qA = q0 + rA, qB = q0 + rB;

    for (int kt = 0; kt < SEQ / 64; kt++) {
        CPA_WAIT0();
        __syncthreads();
        if (kt + 1 < SEQ / 64) { load_kv(kt + 1); CPA_COMMIT(); }

        const uint32_t uKH = sb + KV_BASE + (kt & 1) * KV_STAGE;
        const uint32_t uKL = uKH + KV_BUF;
        const uint32_t uVH = uKH + 2 * KV_BUF;
        const uint32_t uVL = uKH + 3 * KV_BUF;

        float sS[8][4];
#pragma unroll
        for (int f = 0; f < 8; f++)
#pragma unroll
            for (int e = 0; e < 4; e++) sS[f][e] = 0.f;

#pragma unroll
        for (int ks = 0; ks < 4; ks++) {
            const uint32_t qoff = (uint32_t)(qa_row * QSTR + ks * 16 + qa_coff) * 2;
            uint32_t qh[4], ql[4];
            ldsm_x4(qh[0], qh[1], qh[2], qh[3], sb + OFF_QH + qoff);
            ldsm_x4(ql[0], ql[1], ql[2], ql[3], sb + OFF_QL + qoff);
#pragma unroll
            for (int kg = 0; kg < 2; kg++) {
                const uint32_t koff0 =
                    (uint32_t)((kb_key + kg * 32) * QSTR + ks * 16 + kb_coff) * 2;
                const uint32_t koff1 =
                    (uint32_t)((kb_key + kg * 32 + 16) * QSTR + ks * 16 + kb_coff) * 2;
                uint32_t kh0[4], kl0[4], kh1[4], kl1[4];
                ldsm_x4(kh0[0], kh0[1], kh0[2], kh0[3], uKH + koff0);
                ldsm_x4(kl0[0], kl0[1], kl0[2], kl0[3], uKL + koff0);
                ldsm_x4(kh1[0], kh1[1], kh1[2], kh1[3], uKH + koff1);
                ldsm_x4(kl1[0], kl1[1], kl1[2], kl1[3], uKL + koff1);
                float* s0 = sS[4 * kg + 0];
                float* s1 = sS[4 * kg + 1];
                float* s2 = sS[4 * kg + 2];
                float* s3 = sS[4 * kg + 3];
                mma16816(s0, qh, &kh0[0]);
                mma16816(s1, qh, &kh0[2]);
                mma16816(s2, qh, &kh1[0]);
                mma16816(s3, qh, &kh1[2]);
                mma16816(s0, qh, &kl0[0]);
                mma16816(s1, qh, &kl0[2]);
                mma16816(s2, qh, &kl1[0]);
                mma16816(s3, qh, &kl1[2]);
                mma16816(s0, ql, &kh0[0]);
                mma16816(s1, ql, &kh0[2]);
                mma16816(s2, ql, &kh1[0]);
                mma16816(s3, ql, &kh1[2]);
            }
        }

        const int kbase = kt * 64 + (lane & 3) * 2;
#pragma unroll
        for (int f = 0; f < 8; f++) {
#pragma unroll
            for (int e = 0; e < 2; e++) {
                const int kg = kbase + f * 8 + e;
                int dA = kg - qA; dA = dA < 0 ? -dA : dA; if (dA > MAXD - 1) dA = MAXD - 1;
                int dB = kg - qB; dB = dB < 0 ? -dB : dB; if (dB > MAXD - 1) dB = MAXD - 1;
                sS[f][e]     = fmaf(sS[f][e],     0.125f, bias_s[dA]);
                sS[f][2 + e] = fmaf(sS[f][2 + e], 0.125f, bias_s[dB]);
            }
        }

        float mxA = -1e30f, mxB = -1e30f;
#pragma unroll
        for (int f = 0; f < 8; f++) {
            mxA = fmaxf(mxA, fmaxf(sS[f][0], sS[f][1]));
            mxB = fmaxf(mxB, fmaxf(sS[f][2], sS[f][3]));
        }
        mxA = fmaxf(mxA, __shfl_xor_sync(0xffffffffu, mxA, 1));
        mxA = fmaxf(mxA, __shfl_xor_sync(0xffffffffu, mxA, 2));
        mxB = fmaxf(mxB, __shfl_xor_sync(0xffffffffu, mxB, 1));
        mxB = fmaxf(mxB, __shfl_xor_sync(0xffffffffu, mxB, 2));

        const float mnA = fmaxf(m_a, mxA), mnB = fmaxf(m_b, mxB);
        const float facA = __expf(m_a - mnA), facB = __expf(m_b - mnB);
        m_a = mnA; m_b = mnB;

        float sumA = 0.f, sumB = 0.f;
#pragma unroll
        for (int f = 0; f < 8; f++) {
#pragma unroll
            for (int e = 0; e < 2; e++) {
                sS[f][e]     = __expf(sS[f][e]     - m_a); sumA += sS[f][e];
                sS[f][2 + e] = __expf(sS[f][2 + e] - m_b); sumB += sS[f][2 + e];
            }
        }
        sumA += __shfl_xor_sync(0xffffffffu, sumA, 1);
        sumA += __shfl_xor_sync(0xffffffffu, sumA, 2);
        sumB += __shfl_xor_sync(0xffffffffu, sumB, 1);
        sumB += __shfl_xor_sync(0xffffffffu, sumB, 2);
        l_a = l_a * facA + sumA;
        l_b = l_b * facB + sumB;

#pragma unroll
        for (int d = 0; d < 8; d++) {
            accO[d][0] *= facA; accO[d][1] *= facA;
            accO[d][2] *= facB; accO[d][3] *= facB;
        }

#pragma unroll
        for (int ks2 = 0; ks2 < 4; ks2++) {
            uint32_t aH[4], aL[4];
            pack_hilo(sS[2 * ks2][0],     sS[2 * ks2][1],     aH[0], aL[0]);
            pack_hilo(sS[2 * ks2][2],     sS[2 * ks2][3],     aH[1], aL[1]);
            pack_hilo(sS[2 * ks2 + 1][0], sS[2 * ks2 + 1][1], aH[2], aL[2]);
            pack_hilo(sS[2 * ks2 + 1][2], sS[2 * ks2 + 1][3], aH[3], aL[3]);
            const int vrow = vb_key + ks2 * 16;
#pragma unroll
            for (int dp = 0; dp < 2; dp++) {
                const uint32_t voff0 =
                    (uint32_t)(vrow * QSTR + (2 * dp) * 16 + vb_coff) * 2;
                const uint32_t voff1 =
                    (uint32_t)(vrow * QSTR + (2 * dp + 1) * 16 + vb_coff) * 2;
                uint32_t vh0[4], vl0[4], vh1[4], vl1[4];
                ldsm_x4t(vh0[0], vh0[1], vh0[2], vh0[3], uVH + voff0);
                ldsm_x4t(vl0[0], vl0[1], vl0[2], vl0[3], uVL + voff0);
                ldsm_x4t(vh1[0], vh1[1], vh1[2], vh1[3], uVH + voff1);
                ldsm_x4t(vl1[0], vl1[1], vl1[2], vl1[3], uVL + voff1);
                mma16816(accO[4 * dp],     aH, &vh0[0]);
                mma16816(accO[4 * dp + 1], aH, &vh0[2]);
                mma16816(accO[4 * dp + 2], aH, &vh1[0]);
                mma16816(accO[4 * dp + 3], aH, &vh1[2]);
                mma16816(accO[4 * dp],     aH, &vl0[0]);
                mma16816(accO[4 * dp + 1], aH, &vl0[2]);
                mma16816(accO[4 * dp + 2], aH, &vl1[0]);
                mma16816(accO[4 * dp + 3], aH, &vl1[2]);
                mma16816(accO[4 * dp],     aL, &vh0[0]);
                mma16816(accO[4 * dp + 1], aL, &vh0[2]);
                mma16816(accO[4 * dp + 2], aL, &vh1[0]);
                mma16816(accO[4 * dp + 3], aL, &vh1[2]);
            }
        }
    }

    const float invA = 1.f / l_a, invB = 1.f / l_b;
    const int ecol = (lane & 3) * 2;
#pragma unroll
    for (int d = 0; d < 8; d++) {
        uint32_t ph, pl;
        pack_hilo(accO[d][0] * invA, accO[d][1] * invA, ph, pl);
        *(uint32_t*)(ath + (ull)qA * DM + h * DH + d * 8 + ecol) = ph;
        *(uint32_t*)(atl + (ull)qA * DM + h * DH + d * 8 + ecol) = pl;
        pack_hilo(accO[d][2] * invB, accO[d][3] * invB, ph, pl);
        *(uint32_t*)(ath + (ull)qB * DM + h * DH + d * 8 + ecol) = ph;
        *(uint32_t*)(atl + (ull)qB * DM + h * DH + d * 8 + ecol) = pl;
    }
}

// ---------------------------------------------------------------------------
extern "C" void kernel_launch(void* const* d_in, const int* in_sizes, int n_in,
                              void* d_out, int out_size) {
    const float* x        = (const float*)d_in[0];
    const float* w_qkv    = (const float*)d_in[1];
    const float* w_out    = (const float*)d_in[2];
    const float* rel_bias = (const float*)d_in[3];
    float* out = (float*)d_out;

    u16 *xh, *xl, *wqh, *wql, *woh, *wol, *qkvh, *qkvl, *ath, *atl;
    cudaGetSymbolAddress((void**)&xh,   g_xh);
    cudaGetSymbolAddress((void**)&xl,   g_xl);
    cudaGetSymbolAddress((void**)&wqh,  g_wqh);
    cudaGetSymbolAddress((void**)&wql,  g_wql);
    cudaGetSymbolAddress((void**)&woh,  g_woh);
    cudaGetSymbolAddress((void**)&wol,  g_wol);
    cudaGetSymbolAddress((void**)&qkvh, g_qkvh);
    cudaGetSymbolAddress((void**)&qkvl, g_qkvl);
    cudaGetSymbolAddress((void**)&ath,  g_ath);
    cudaGetSymbolAddress((void**)&atl,  g_atl);

    cudaFuncSetAttribute(gemm_bf16_v2<true>,  cudaFuncAttributeMaxDynamicSharedMemorySize, GSMEM);
    cudaFuncSetAttribute(gemm_bf16_v2<false>, cudaFuncAttributeMaxDynamicSharedMemorySize, GSMEM);
    cudaFuncSetAttribute(attn_mma, cudaFuncAttributeMaxDynamicSharedMemorySize, ATT_SMEM);

    // 0) one-time splits, single launch for all three tensors
    {
        const int total = (NX + NW + NO) / 4;
        conv_split_all<<<(total + 255) / 256, 256>>>(x, w_qkv, w_out,
                                                     xh, xl, wqh, wql, woh, wol);
    }

    // 1) qkv = x @ w_qkv  -> bf16 hi/lo   (R10 2D grid, best measured)
    gemm_bf16_v2<true><<<dim3(TDM / 128, SEQ / 64), 128, GSMEM>>>(
        xh, xl, wqh, wql, nullptr, qkvh, qkvl, SEQ, TDM, DM);

    // 2) attention (BQ=128, warp-owns-row) -> bf16 hi/lo
    attn_mma<<<dim3(SEQ / 128, NH), 256, ATT_SMEM>>>(qkvh, qkvl, rel_bias, ath, atl);

    // 3) out = attn @ w_out -> fp32
    gemm_bf16_v2<false><<<dim3(DM / 128, SEQ / 64), 128, GSMEM>>>(
        ath, atl, woh, wol, out, nullptr, nullptr, SEQ, DM, DM);
}

// round 16
// speedup vs baseline: 1.0481x; 1.0013x over previous
#include <cuda_runtime.h>
#include <cuda_bf16.h>
#include <cstdint>
#include <math.h>

#define SEQ  2048
#define DM   1024
#define TDM  3072
#define NH   16
#define DH   64
#define MAXD 128

typedef unsigned long long ull;
typedef unsigned short u16;

// ---------------- persistent scratch (bf16 hi/lo split form) ----------------
__device__ u16 g_xh[SEQ * DM],  g_xl[SEQ * DM];
__device__ u16 g_wqh[DM * TDM], g_wql[DM * TDM];
__device__ u16 g_woh[DM * DM],  g_wol[DM * DM];
__device__ u16 g_qkvh[SEQ * TDM], g_qkvl[SEQ * TDM];
__device__ u16 g_ath[SEQ * DM],   g_atl[SEQ * DM];

// ---------------- helpers ---------------------------------------------------
__device__ __forceinline__ uint32_t smem_u32(const void* p) {
    uint32_t a;
    asm("{ .reg .u64 t; cvta.to.shared.u64 t, %1; cvt.u32.u64 %0, t; }" : "=r"(a) : "l"(p));
    return a;
}
__device__ __forceinline__ void cpa16(uint32_t dst, const void* src) {
    asm volatile("cp.async.cg.shared.global [%0], [%1], 16;" :: "r"(dst), "l"(src));
}
#define CPA_COMMIT() asm volatile("cp.async.commit_group;" ::: "memory")
#define CPA_WAIT0()  asm volatile("cp.async.wait_group 0;" ::: "memory")

__device__ __forceinline__ void ldsm_x4(uint32_t& r0, uint32_t& r1, uint32_t& r2,
                                        uint32_t& r3, uint32_t addr) {
    asm volatile("ldmatrix.sync.aligned.m8n8.x4.shared.b16 {%0,%1,%2,%3}, [%4];"
                 : "=r"(r0), "=r"(r1), "=r"(r2), "=r"(r3) : "r"(addr));
}
__device__ __forceinline__ void ldsm_x4t(uint32_t& r0, uint32_t& r1, uint32_t& r2,
                                         uint32_t& r3, uint32_t addr) {
    asm volatile("ldmatrix.sync.aligned.m8n8.x4.trans.shared.b16 {%0,%1,%2,%3}, [%4];"
                 : "=r"(r0), "=r"(r1), "=r"(r2), "=r"(r3) : "r"(addr));
}
__device__ __forceinline__ void mma16816(float* d, const uint32_t* a, const uint32_t* b) {
    asm volatile("mma.sync.aligned.m16n8k16.row.col.f32.bf16.bf16.f32 "
                 "{%0,%1,%2,%3}, {%4,%5,%6,%7}, {%8,%9}, {%0,%1,%2,%3};"
                 : "+f"(d[0]), "+f"(d[1]), "+f"(d[2]), "+f"(d[3])
                 : "r"(a[0]), "r"(a[1]), "r"(a[2]), "r"(a[3]), "r"(b[0]), "r"(b[1]));
}
__device__ __forceinline__ uint32_t bf16x2_of(float lo, float hi) {
    uint32_t r;
    asm("cvt.rn.bf16x2.f32 %0, %1, %2;" : "=r"(r) : "f"(hi), "f"(lo));
    return r;
}
__device__ __forceinline__ void pack_hilo(float x, float y, uint32_t& ph, uint32_t& pl) {
    __nv_bfloat16 hx = __float2bfloat16_rn(x);
    __nv_bfloat16 hy = __float2bfloat16_rn(y);
    float fx = __bfloat162float(hx), fy = __bfloat162float(hy);
    ph = ((uint32_t)__bfloat16_as_ushort(hy) << 16) | (uint32_t)__bfloat16_as_ushort(hx);
    pl = bf16x2_of(x - fx, y - fy);
}

// ---------------------------------------------------------------------------
// One-time fp32 -> (hi,lo) bf16 split, ALL THREE tensors in one launch.
// ---------------------------------------------------------------------------
#define NX (SEQ * DM)
#define NW (DM * TDM)
#define NO (DM * DM)

__global__ __launch_bounds__(256)
void conv_split_all(const float* __restrict__ x, const float* __restrict__ wq,
                    const float* __restrict__ wo,
                    u16* __restrict__ xh, u16* __restrict__ xl,
                    u16* __restrict__ wqh, u16* __restrict__ wql,
                    u16* __restrict__ woh, u16* __restrict__ wol) {
    int i = (blockIdx.x * 256 + threadIdx.x) * 4;
    const float* src;
    u16 *hi, *lo;
    if (i < NX) {
        src = x; hi = xh; lo = xl;
    } else if (i < NX + NW) {
        i -= NX; src = wq; hi = wqh; lo = wql;
    } else if (i < NX + NW + NO) {
        i -= NX + NW; src = wo; hi = woh; lo = wol;
    } else {
        return;
    }
    float4 v = *(const float4*)(src + i);
    uint32_t h0, l0, h1, l1;
    pack_hilo(v.x, v.y, h0, l0);
    pack_hilo(v.z, v.w, h1, l1);
    *(uint32_t*)(hi + i)     = h0;
    *(uint32_t*)(hi + i + 2) = h1;
    *(uint32_t*)(lo + i)     = l0;
    *(uint32_t*)(lo + i + 2) = l1;
}

// ---------------------------------------------------------------------------
// Pure-bf16 split GEMM (R10, best measured): C = A @ B -> bf16 hi/lo.
// CTA 64x128, 128 threads = 4 warps (2 wm x 2 wn), warp tile 32x64.
// ---------------------------------------------------------------------------
#define SA 40
#define SB 136
#define A_T_B 5120
#define B_T_B 8704
#define STAGE_B (2 * A_T_B + 2 * B_T_B)   // 27648
#define GSMEM   (2 * STAGE_B)             // 55296

__global__ __launch_bounds__(128, 4)
void gemm_bf16_v2(const u16* __restrict__ Ah, const u16* __restrict__ Al,
                  const u16* __restrict__ Bh, const u16* __restrict__ Bl,
                  u16* __restrict__ Ch, u16* __restrict__ Cl,
                  int M, int N, int K) {
    extern __shared__ char smem[];
    const uint32_t smem_b = smem_u32(smem);
    const int tid  = threadIdx.x;
    const int lane = tid & 31;
    const int wid  = tid >> 5;
    const int wm   = wid & 1;
    const int wn   = wid >> 1;
    const int bm = blockIdx.y * 64;
    const int bn = blockIdx.x * 128;

    auto load_stage = [&](int t) {
        const uint32_t stg = smem_b + (t & 1) * STAGE_B;
#pragma unroll
        for (int i = 0; i < 2; i++) {
            const int c = tid + i * 128;
            const int row = c >> 2, cc = c & 3;
            const ull sa = (ull)(bm + row) * K + t * 32 + cc * 8;
            cpa16(stg + row * 80 + cc * 16,         Ah + sa);
            cpa16(stg + A_T_B + row * 80 + cc * 16, Al + sa);
        }
#pragma unroll
        for (int i = 0; i < 4; i++) {
            const int c = tid + i * 128;
            const int rb = c >> 4, cb = c & 15;
            const ull sbp = (ull)(t * 32 + rb) * N + bn + cb * 8;
            cpa16(stg + 2 * A_T_B + rb * 272 + cb * 16,         Bh + sbp);
            cpa16(stg + 2 * A_T_B + B_T_B + rb * 272 + cb * 16, Bl + sbp);
        }
    };

    float accM0[8][4], accM1[8][4];
#pragma unroll
    for (int nt = 0; nt < 8; nt++)
#pragma unroll
        for (int e = 0; e < 4; e++) { accM0[nt][e] = 0.f; accM1[nt][e] = 0.f; }

    const int NT = K / 32;
    load_stage(0);
    CPA_COMMIT();

    for (int t = 0; t < NT; t++) {
        CPA_WAIT0();
        __syncthreads();
        if (t + 1 < NT) { load_stage(t + 1); CPA_COMMIT(); }

        const uint32_t stg  = smem_b + (t & 1) * STAGE_B;
        const uint32_t uAhi = stg;
        const uint32_t uAlo = stg + A_T_B;
        const uint32_t uBhi = stg + 2 * A_T_B;
        const uint32_t uBlo = uBhi + B_T_B;
#pragma unroll
        for (int ks = 0; ks < 2; ks++) {
            const int k0 = ks * 16;
            uint32_t afh0[4], afl0[4], afh1[4], afl1[4];
            {
                const int row0 = wm * 32 + (lane & 15);
                const int col = k0 + ((lane >> 4) << 3);
                const uint32_t off0 = (uint32_t)(row0 * SA + col) * 2;
                const uint32_t off1 = (uint32_t)((row0 + 16) * SA + col) * 2;
                ldsm_x4(afh0[0], afh0[1], afh0[2], afh0[3], uAhi + off0);
                ldsm_x4(afl0[0], afl0[1], afl0[2], afl0[3], uAlo + off0);
                ldsm_x4(afh1[0], afh1[1], afh1[2], afh1[3], uAhi + off1);
                ldsm_x4(afl1[0], afl1[1], afl1[2], afl1[3], uAlo + off1);
            }
#pragma unroll
            for (int g = 0; g < 4; g++) {
                uint32_t bh[4], bl[4];
                const int row = k0 + (lane & 15);
                const int col = wn * 64 + g * 16 + ((lane >> 4) << 3);
                const uint32_t off = (uint32_t)(row * SB + col) * 2;
                ldsm_x4t(bh[0], bh[1], bh[2], bh[3], uBhi + off);
                ldsm_x4t(bl[0], bl[1], bl[2], bl[3], uBlo + off);
                // hh
                mma16816(accM0[2 * g],     afh0, &bh[0]);
                mma16816(accM0[2 * g + 1], afh0, &bh[2]);
                mma16816(accM1[2 * g],     afh1, &bh[0]);
                mma16816(accM1[2 * g + 1], afh1, &bh[2]);
                // hl
                mma16816(accM0[2 * g],     afh0, &bl[0]);
                mma16816(accM0[2 * g + 1], afh0, &bl[2]);
                mma16816(accM1[2 * g],     afh1, &bl[0]);
                mma16816(accM1[2 * g + 1], afh1, &bl[2]);
                // lh
                mma16816(accM0[2 * g],     afl0, &bh[0]);
                mma16816(accM0[2 * g + 1], afl0, &bh[2]);
                mma16816(accM1[2 * g],     afl1, &bh[0]);
                mma16816(accM1[2 * g + 1], afl1, &bh[2]);
            }
        }
    }

    // ---- epilogue: bf16 hi/lo ----
    const int group = lane >> 2;
    const int tq = lane & 3;
#pragma unroll
    for (int mt = 0; mt < 2; mt++) {
#pragma unroll
        for (int nt = 0; nt < 8; nt++) {
            float* a = (mt == 0) ? accM0[nt] : accM1[nt];
            const int row = bm + wm * 32 + mt * 16 + group;
            const int col = bn + wn * 64 + nt * 8 + tq * 2;
            uint32_t ph, pl;
            pack_hilo(a[0], a[1], ph, pl);
            *(uint32_t*)(Ch + (ull)row * N + col) = ph;
            *(uint32_t*)(Cl + (ull)row * N + col) = pl;
            pack_hilo(a[2], a[3], ph, pl);
            *(uint32_t*)(Ch + (ull)(row + 8) * N + col) = ph;
            *(uint32_t*)(Cl + (ull)(row + 8) * N + col) = pl;
        }
    }
}

// ---------------------------------------------------------------------------
// 64x64-tile bf16 split GEMM for the out-projection (fp32 output).
// 128 threads = 4 warps (2 wm x 2 wn), warp tile 32x32. Grid 512 -> high fill.
// ---------------------------------------------------------------------------
#define SB2 72
#define B2_T_B 4608                        // 32*72*2
#define STAGE2_B (2 * A_T_B + 2 * B2_T_B)  // 19456
#define GSMEM2   (2 * STAGE2_B)            // 38912

__global__ __launch_bounds__(128, 4)
void gemm_bf16_64(const u16* __restrict__ Ah, const u16* __restrict__ Al,
                  const u16* __restrict__ Bh, const u16* __restrict__ Bl,
                  float* __restrict__ Cf, int M, int N, int K) {
    extern __shared__ char smem[];
    const uint32_t smem_b = smem_u32(smem);
    const int tid  = threadIdx.x;
    const int lane = tid & 31;
    const int wid  = tid >> 5;
    const int wm   = wid & 1;
    const int wn   = wid >> 1;
    const int bm = blockIdx.y * 64;
    const int bn = blockIdx.x * 64;

    auto load_stage = [&](int t) {
        const uint32_t stg = smem_b + (t & 1) * STAGE2_B;
#pragma unroll
        for (int i = 0; i < 2; i++) {
            const int c = tid + i * 128;
            const int row = c >> 2, cc = c & 3;
            const ull sa = (ull)(bm + row) * K + t * 32 + cc * 8;
            cpa16(stg + row * 80 + cc * 16,         Ah + sa);
            cpa16(stg + A_T_B + row * 80 + cc * 16, Al + sa);
        }
#pragma unroll
        for (int i = 0; i < 2; i++) {
            const int c = tid + i * 128;
            const int rb = c >> 3, cb = c & 7;
            const ull sbp = (ull)(t * 32 + rb) * N + bn + cb * 8;
            cpa16(stg + 2 * A_T_B + rb * 144 + cb * 16,          Bh + sbp);
            cpa16(stg + 2 * A_T_B + B2_T_B + rb * 144 + cb * 16, Bl + sbp);
        }
    };

    float accM0[4][4], accM1[4][4];
#pragma unroll
    for (int nt = 0; nt < 4; nt++)
#pragma unroll
        for (int e = 0; e < 4; e++) { accM0[nt][e] = 0.f; accM1[nt][e] = 0.f; }

    const int NT = K / 32;
    load_stage(0);
    CPA_COMMIT();

    for (int t = 0; t < NT; t++) {
        CPA_WAIT0();
        __syncthreads();
        if (t + 1 < NT) { load_stage(t + 1); CPA_COMMIT(); }

        const uint32_t stg  = smem_b + (t & 1) * STAGE2_B;
        const uint32_t uAhi = stg;
        const uint32_t uAlo = stg + A_T_B;
        const uint32_t uBhi = stg + 2 * A_T_B;
        const uint32_t uBlo = uBhi + B2_T_B;
#pragma unroll
        for (int ks = 0; ks < 2; ks++) {
            const int k0 = ks * 16;
            uint32_t afh0[4], afl0[4], afh1[4], afl1[4];
            {
                const int row0 = wm * 32 + (lane & 15);
                const int col = k0 + ((lane >> 4) << 3);
                const uint32_t off0 = (uint32_t)(row0 * SA + col) * 2;
                const uint32_t off1 = (uint32_t)((row0 + 16) * SA + col) * 2;
                ldsm_x4(afh0[0], afh0[1], afh0[2], afh0[3], uAhi + off0);
                ldsm_x4(afl0[0], afl0[1], afl0[2], afl0[3], uAlo + off0);
                ldsm_x4(afh1[0], afh1[1], afh1[2], afh1[3], uAhi + off1);
                ldsm_x4(afl1[0], afl1[1], afl1[2], afl1[3], uAlo + off1);
            }
#pragma unroll
            for (int g = 0; g < 2; g++) {
                uint32_t bh[4], bl[4];
                const int row = k0 + (lane & 15);
                const int col = wn * 32 + g * 16 + ((lane >> 4) << 3);
                const uint32_t off = (uint32_t)(row * SB2 + col) * 2;
                ldsm_x4t(bh[0], bh[1], bh[2], bh[3], uBhi + off);
                ldsm_x4t(bl[0], bl[1], bl[2], bl[3], uBlo + off);
                // hh
                mma16816(accM0[2 * g],     afh0, &bh[0]);
                mma16816(accM0[2 * g + 1], afh0, &bh[2]);
                mma16816(accM1[2 * g],     afh1, &bh[0]);
                mma16816(accM1[2 * g + 1], afh1, &bh[2]);
                // hl
                mma16816(accM0[2 * g],     afh0, &bl[0]);
                mma16816(accM0[2 * g + 1], afh0, &bl[2]);
                mma16816(accM1[2 * g],     afh1, &bl[0]);
                mma16816(accM1[2 * g + 1], afh1, &bl[2]);
                // lh
                mma16816(accM0[2 * g],     afl0, &bh[0]);
                mma16816(accM0[2 * g + 1], afl0, &bh[2]);
                mma16816(accM1[2 * g],     afl1, &bh[0]);
                mma16816(accM1[2 * g + 1], afl1, &bh[2]);
            }
        }
    }

    // ---- epilogue: fp32 ----
    const int group = lane >> 2;
    const int tq = lane & 3;
#pragma unroll
    for (int mt = 0; mt < 2; mt++) {
#pragma unroll
        for (int nt = 0; nt < 4; nt++) {
            float* a = (mt == 0) ? accM0[nt] : accM1[nt];
            const int row = bm + wm * 32 + mt * 16 + group;
            const int col = bn + wn * 32 + nt * 8 + tq * 2;
            *(float2*)&Cf[(ull)row * N + col] = make_float2(a[0], a[1]);
            *(float2*)&Cf[(ull)(row + 8) * N + col] = make_float2(a[2], a[3]);
        }
    }
}

// ---------------------------------------------------------------------------
// HMMA flash attention, BQ=128 (R8, validated): 8 warps x 16 q-rows x 64 keys.
// ---------------------------------------------------------------------------
#define QSTR 72
#define Q_BUF 18432
#define OFF_QH 0
#define OFF_QL Q_BUF
#define KV_BASE (2 * Q_BUF)
#define KV_BUF 9216
#define KV_STAGE (4 * KV_BUF)
#define OFF_BIAS (KV_BASE + 2 * KV_STAGE)
#define ATT_SMEM (OFF_BIAS + 512)

__global__ __launch_bounds__(256, 2)
void attn_mma(const u16* __restrict__ qkvh, const u16* __restrict__ qkvl,
              const float* __restrict__ rel_bias,
              u16* __restrict__ ath, u16* __restrict__ atl) {
    extern __shared__ char sm[];
    const uint32_t sb = smem_u32(sm);
    const int tid  = threadIdx.x;
    const int lane = tid & 31;
    const int wm   = tid >> 5;
    const int h  = blockIdx.y;
    const int q0 = blockIdx.x * 128;

    float* bias_s = (float*)(sm + OFF_BIAS);
    if (tid < MAXD) bias_s[tid] = rel_bias[tid * NH + h];

    auto load_kv = [&](int kt) {
        const uint32_t sK = sb + KV_BASE + (kt & 1) * KV_STAGE;
        const ull base = (ull)(kt * 64) * TDM + h * DH;
#pragma unroll
        for (int i = 0; i < 2; i++) {
            const int c = tid + i * 256;
            const int row = c >> 3, cc = c & 7;
            const ull so = base + (ull)row * TDM + cc * 8;
            const uint32_t d = row * 144 + cc * 16;
            cpa16(sK + d,              qkvh + so + DM);
            cpa16(sK + KV_BUF + d,     qkvl + so + DM);
            cpa16(sK + 2 * KV_BUF + d, qkvh + so + 2 * DM);
            cpa16(sK + 3 * KV_BUF + d, qkvl + so + 2 * DM);
        }
    };

#pragma unroll
    for (int i = 0; i < 4; i++) {
        const int c = tid + i * 256;
        const int row = c >> 3, cc = c & 7;
        const ull so = (ull)(q0 + row) * TDM + h * DH + cc * 8;
        const uint32_t d = row * 144 + cc * 16;
        cpa16(sb + OFF_QH + d, qkvh + so);
        cpa16(sb + OFF_QL + d, qkvl + so);
    }
    load_kv(0);
    CPA_COMMIT();

    float m_a = -1e30f, m_b = -1e30f, l_a = 0.f, l_b = 0.f;
    float accO[8][4];
#pragma unroll
    for (int d = 0; d < 8; d++)
#pragma unroll
        for (int e = 0; e < 4; e++) accO[d][e] = 0.f;

    const int qa_row  = wm * 16 + (lane & 15);
    const int qa_coff = (lane >> 4) << 3;
    const int kb_key  = ((lane >> 4) << 3) + (lane & 7);
    const int kb_coff = ((lane >> 3) & 1) << 3;
    const int vb_key  = lane & 15;
    const int vb_coff = (lane >> 4) << 3;
    const int rA = wm * 16 + (lane >> 2);
    const int rB = rA + 8;
    const int qA = q0 + rA, qB = q0 + rB;

    for (int kt = 0; kt < SEQ / 64; kt++) {
        CPA_WAIT0();
        __syncthreads();
        if (kt + 1 < SEQ / 64) { load_kv(kt + 1); CPA_COMMIT(); }

        const uint32_t uKH = sb + KV_BASE + (kt & 1) * KV_STAGE;
        const uint32_t uKL = uKH + KV_BUF;
        const uint32_t uVH = uKH + 2 * KV_BUF;
        const uint32_t uVL = uKH + 3 * KV_BUF;

        float sS[8][4];
#pragma unroll
        for (int f = 0; f < 8; f++)
#pragma unroll
            for (int e = 0; e < 4; e++) sS[f][e] = 0.f;

#pragma unroll
        for (int ks = 0; ks < 4; ks++) {
            const uint32_t qoff = (uint32_t)(qa_row * QSTR + ks * 16 + qa_coff) * 2;
            uint32_t qh[4], ql[4];
            ldsm_x4(qh[0], qh[1], qh[2], qh[3], sb + OFF_QH + qoff);
            ldsm_x4(ql[0], ql[1], ql[2], ql[3], sb + OFF_QL + qoff);
#pragma unroll
            for (int kg = 0; kg < 2; kg++) {
                const uint32_t koff0 =
                    (uint32_t)((kb_key + kg * 32) * QSTR + ks * 16 + kb_coff) * 2;
                const uint32_t koff1 =
                    (uint32_t)((kb_key + kg * 32 + 16) * QSTR + ks * 16 + kb_coff) * 2;
                uint32_t kh0[4], kl0[4], kh1[4], kl1[4];
                ldsm_x4(kh0[0], kh0[1], kh0[2], kh0[3], uKH + koff0);
                ldsm_x4(kl0[0], kl0[1], kl0[2], kl0[3], uKL + koff0);
                ldsm_x4(kh1[0], kh1[1], kh1[2], kh1[3], uKH + koff1);
                ldsm_x4(kl1[0], kl1[1], kl1[2], kl1[3], uKL + koff1);
                float* s0 = sS[4 * kg + 0];
                float* s1 = sS[4 * kg + 1];
                float* s2 = sS[4 * kg + 2];
                float* s3 = sS[4 * kg + 3];
                mma16816(s0, qh, &kh0[0]);
                mma16816(s1, qh, &kh0[2]);
                mma16816(s2, qh, &kh1[0]);
                mma16816(s3, qh, &kh1[2]);
                mma16816(s0, qh, &kl0[0]);
                mma16816(s1, qh, &kl0[2]);
                mma16816(s2, qh, &kl1[0]);
                mma16816(s3, qh, &kl1[2]);
                mma16816(s0, ql, &kh0[0]);
                mma16816(s1, ql, &kh0[2]);
                mma16816(s2, ql, &kh1[0]);
                mma16816(s3, ql, &kh1[2]);
            }
        }

        const int kbase = kt * 64 + (lane & 3) * 2;
#pragma unroll
        for (int f = 0; f < 8; f++) {
#pragma unroll
            for (int e = 0; e < 2; e++) {
                const int kg = kbase + f * 8 + e;
                int dA = kg - qA; dA = dA < 0 ? -dA : dA; if (dA > MAXD - 1) dA = MAXD - 1;
                int dB = kg - qB; dB = dB < 0 ? -dB : dB; if (dB > MAXD - 1) dB = MAXD - 1;
                sS[f][e]     = fmaf(sS[f][e],     0.125f, bias_s[dA]);
                sS[f][2 + e] = fmaf(sS[f][2 + e], 0.125f, bias_s[dB]);
            }
        }

        float mxA = -1e30f, mxB = -1e30f;
#pragma unroll
        for (int f = 0; f < 8; f++) {
            mxA = fmaxf(mxA, fmaxf(sS[f][0], sS[f][1]));
            mxB = fmaxf(mxB, fmaxf(sS[f][2], sS[f][3]));
        }
        mxA = fmaxf(mxA, __shfl_xor_sync(0xffffffffu, mxA, 1));
        mxA = fmaxf(mxA, __shfl_xor_sync(0xffffffffu, mxA, 2));
        mxB = fmaxf(mxB, __shfl_xor_sync(0xffffffffu, mxB, 1));
        mxB = fmaxf(mxB, __shfl_xor_sync(0xffffffffu, mxB, 2));

        const float mnA = fmaxf(m_a, mxA), mnB = fmaxf(m_b, mxB);
        const float facA = __expf(m_a - mnA), facB = __expf(m_b - mnB);
        m_a = mnA; m_b = mnB;

        float sumA = 0.f, sumB = 0.f;
#pragma unroll
        for (int f = 0; f < 8; f++) {
#pragma unroll
            for (int e = 0; e < 2; e++) {
                sS[f][e]     = __expf(sS[f][e]     - m_a); sumA += sS[f][e];
                sS[f][2 + e] = __expf(sS[f][2 + e] - m_b); sumB += sS[f][2 + e];
            }
        }
        sumA += __shfl_xor_sync(0xffffffffu, sumA, 1);
        sumA += __shfl_xor_sync(0xffffffffu, sumA, 2);
        sumB += __shfl_xor_sync(0xffffffffu, sumB, 1);
        sumB += __shfl_xor_sync(0xffffffffu, sumB, 2);
        l_a = l_a * facA + sumA;
        l_b = l_b * facB + sumB;

#pragma unroll
        for (int d = 0; d < 8; d++) {
            accO[d][0] *= facA; accO[d][1] *= facA;
            accO[d][2] *= facB; accO[d][3] *= facB;
        }

#pragma unroll
        for (int ks2 = 0; ks2 < 4; ks2++) {
            uint32_t aH[4], aL[4];
            pack_hilo(sS[2 * ks2][0],     sS[2 * ks2][1],     aH[0], aL[0]);
            pack_hilo(sS[2 * ks2][2],     sS[2 * ks2][3],     aH[1], aL[1]);
            pack_hilo(sS[2 * ks2 + 1][0], sS[2 * ks2 + 1][1], aH[2], aL[2]);
            pack_hilo(sS[2 * ks2 + 1][2], sS[2 * ks2 + 1][3], aH[3], aL[3]);
            const int vrow = vb_key + ks2 * 16;
#pragma unroll
            for (int dp = 0; dp < 2; dp++) {
                const uint32_t voff0 =
                    (uint32_t)(vrow * QSTR + (2 * dp) * 16 + vb_coff) * 2;
                const uint32_t voff1 =
                    (uint32_t)(vrow * QSTR + (2 * dp + 1) * 16 + vb_coff) * 2;
                uint32_t vh0[4], vl0[4], vh1[4], vl1[4];
                ldsm_x4t(vh0[0], vh0[1], vh0[2], vh0[3], uVH + voff0);
                ldsm_x4t(vl0[0], vl0[1], vl0[2], vl0[3], uVL + voff0);
                ldsm_x4t(vh1[0], vh1[1], vh1[2], vh1[3], uVH + voff1);
                ldsm_x4t(vl1[0], vl1[1], vl1[2], vl1[3], uVL + voff1);
                mma16816(accO[4 * dp],     aH, &vh0[0]);
                mma16816(accO[4 * dp + 1], aH, &vh0[2]);
                mma16816(accO[4 * dp + 2], aH, &vh1[0]);
                mma16816(accO[4 * dp + 3], aH, &vh1[2]);
                mma16816(accO[4 * dp],     aH, &vl0[0]);
                mma16816(accO[4 * dp + 1], aH, &vl0[2]);
                mma16816(accO[4 * dp + 2], aH, &vl1[0]);
                mma16816(accO[4 * dp + 3], aH, &vl1[2]);
                mma16816(accO[4 * dp],     aL, &vh0[0]);
                mma16816(accO[4 * dp + 1], aL, &vh0[2]);
                mma16816(accO[4 * dp + 2], aL, &vh1[0]);
                mma16816(accO[4 * dp + 3], aL, &vh1[2]);
            }
        }
    }

    const float invA = 1.f / l_a, invB = 1.f / l_b;
    const int ecol = (lane & 3) * 2;
#pragma unroll
    for (int d = 0; d < 8; d++) {
        uint32_t ph, pl;
        pack_hilo(accO[d][0] * invA, accO[d][1] * invA, ph, pl);
        *(uint32_t*)(ath + (ull)qA * DM + h * DH + d * 8 + ecol) = ph;
        *(uint32_t*)(atl + (ull)qA * DM + h * DH + d * 8 + ecol) = pl;
        pack_hilo(accO[d][2] * invB, accO[d][3] * invB, ph, pl);
        *(uint32_t*)(ath + (ull)qB * DM + h * DH + d * 8 + ecol) = ph;
        *(uint32_t*)(atl + (ull)qB * DM + h * DH + d * 8 + ecol) = pl;
    }
}

// ---------------------------------------------------------------------------
extern "C" void kernel_launch(void* const* d_in, const int* in_sizes, int n_in,
                              void* d_out, int out_size) {
    const float* x        = (const float*)d_in[0];
    const float* w_qkv    = (const float*)d_in[1];
    const float* w_out    = (const float*)d_in[2];
    const float* rel_bias = (const float*)d_in[3];
    float* out = (float*)d_out;

    u16 *xh, *xl, *wqh, *wql, *woh, *wol, *qkvh, *qkvl, *ath, *atl;
    cudaGetSymbolAddress((void**)&xh,   g_xh);
    cudaGetSymbolAddress((void**)&xl,   g_xl);
    cudaGetSymbolAddress((void**)&wqh,  g_wqh);
    cudaGetSymbolAddress((void**)&wql,  g_wql);
    cudaGetSymbolAddress((void**)&woh,  g_woh);
    cudaGetSymbolAddress((void**)&wol,  g_wol);
    cudaGetSymbolAddress((void**)&qkvh, g_qkvh);
    cudaGetSymbolAddress((void**)&qkvl, g_qkvl);
    cudaGetSymbolAddress((void**)&ath,  g_ath);
    cudaGetSymbolAddress((void**)&atl,  g_atl);

    cudaFuncSetAttribute(gemm_bf16_v2, cudaFuncAttributeMaxDynamicSharedMemorySize, GSMEM);
    cudaFuncSetAttribute(gemm_bf16_64, cudaFuncAttributeMaxDynamicSharedMemorySize, GSMEM2);
    cudaFuncSetAttribute(attn_mma, cudaFuncAttributeMaxDynamicSharedMemorySize, ATT_SMEM);

    // 0) one-time splits, single launch for all three tensors
    {
        const int total = (NX + NW + NO) / 4;
        conv_split_all<<<(total + 255) / 256, 256>>>(x, w_qkv, w_out,
                                                     xh, xl, wqh, wql, woh, wol);
    }

    // 1) qkv = x @ w_qkv  -> bf16 hi/lo   (64x128 tiles)
    gemm_bf16_v2<<<dim3(TDM / 128, SEQ / 64), 128, GSMEM>>>(
        xh, xl, wqh, wql, qkvh, qkvl, SEQ, TDM, DM);

    // 2) attention (BQ=128, warp-owns-row) -> bf16 hi/lo
    attn_mma<<<dim3(SEQ / 128, NH), 256, ATT_SMEM>>>(qkvh, qkvl, rel_bias, ath, atl);

    // 3) out = attn @ w_out -> fp32   (64x64 tiles, grid 512 for occupancy fill)
    gemm_bf16_64<<<dim3(DM / 64, SEQ / 64), 128, GSMEM2>>>(
        ath, atl, woh, wol, out, SEQ, DM, DM);
}